// round 5
// baseline (speedup 1.0000x reference)
#include <cuda_runtime.h>
#include <cuda_bf16.h>
#include <math.h>
#include <stdint.h>

#define Bz 32
#define NS 4096
#define Dm 256
#define Hh 4
#define DH 64
#define Ll 6
#define NQ 512
#define NK 1024
#define ATT_SCALE 0.125f

// ---------------- scratch (device globals; no allocation allowed) ----------------
__device__ float g_upd[(size_t)Bz * NS * Dm];   // running update_tensor state
__device__ float g_qn [(size_t)Bz * NQ * Dm];
__device__ float g_kn [(size_t)Bz * NK * Dm];
__device__ float g_Q  [(size_t)Bz * NQ * Dm];
__device__ float g_K  [(size_t)Bz * NK * Dm];
__device__ float g_V  [(size_t)Bz * NK * Dm];
__device__ float g_ctx[(size_t)Bz * NQ * Dm];
__device__ float g_h  [(size_t)Bz * NQ * Dm];
__device__ float g_t  [(size_t)Bz * NQ * Dm];
__device__ float g_r  [(size_t)Bz * NQ * Dm];
// prepped weights: 6 matrices x 12 chunks x 256 rows x 64 bf16 (pre-swizzled SMEM image)
__device__ __nv_bfloat16 g_wprep[(size_t)6 * 12 * 256 * 64];

// ---------------- small helpers ----------------
__device__ __forceinline__ uint32_t smem_u32(const void* p) {
    uint32_t a;
    asm("{ .reg .u64 t; cvta.to.shared.u64 t, %1; cvt.u32.u64 %0, t; }" : "=r"(a) : "l"(p));
    return a;
}
__device__ __forceinline__ uint32_t elect_one_pred() {
    uint32_t pred;
    asm volatile(
        "{\n\t.reg .pred p;\n\telect.sync _|p, 0xFFFFFFFF;\n\tselp.b32 %0, 1, 0, p;\n\t}"
        : "=r"(pred));
    return pred;
}
__device__ __forceinline__ unsigned short f2bf(float x) {
    __nv_bfloat16 b = __float2bfloat16_rn(x);
    return *reinterpret_cast<unsigned short*>(&b);
}
__device__ __forceinline__ unsigned short f2bf_lo(float x) {
    __nv_bfloat16 b = __float2bfloat16_rn(x);
    float hi = __bfloat162float(b);
    __nv_bfloat16 l = __float2bfloat16_rn(x - hi);
    return *reinterpret_cast<unsigned short*>(&l);
}

__device__ __forceinline__ float2 block_meanrstd(float x, float* red) {
    float s1 = x, s2 = x * x;
    #pragma unroll
    for (int o = 16; o > 0; o >>= 1) {
        s1 += __shfl_xor_sync(0xffffffffu, s1, o);
        s2 += __shfl_xor_sync(0xffffffffu, s2, o);
    }
    int w = threadIdx.x >> 5, ln = threadIdx.x & 31;
    if (ln == 0) { red[w] = s1; red[8 + w] = s2; }
    __syncthreads();
    float m = 0.f, q = 0.f;
    #pragma unroll
    for (int i = 0; i < 8; i++) { m += red[i]; q += red[8 + i]; }
    __syncthreads();
    m *= (1.0f / Dm);
    q = q * (1.0f / Dm) - m * m;
    return make_float2(m, rsqrtf(fmaxf(q, 0.f) + 1e-5f));
}

__device__ __forceinline__ float gelu_tanh(float x) {
    const float c = 0.7978845608028654f;
    float t = tanhf(c * (x + 0.044715f * x * x * x));
    return 0.5f * x * (1.0f + t);
}

// ---------------- tcgen05 plumbing (only instantiated under sm_103a feature) ----------------
#define MBAR_INIT(addr, cnt) \
    asm volatile("mbarrier.init.shared.b64 [%0], %1;" :: "r"(addr), "r"(cnt) : "memory")
#define MBAR_INVAL(addr) \
    asm volatile("mbarrier.inval.shared.b64 [%0];" :: "r"(addr) : "memory")
#define MBAR_WAIT(addr, par) do { \
    uint32_t _m = (addr); uint32_t _p = (par); uint32_t _d; \
    asm volatile("{\n\t.reg .pred p;\n\t" \
        "mbarrier.try_wait.parity.acquire.cta.shared::cta.b64 p, [%1], %2;\n\t" \
        "selp.b32 %0, 1, 0, p;\n\t}" : "=r"(_d) : "r"(_m), "r"(_p) : "memory"); \
    if (!_d) { \
        asm volatile("{\n\t.reg .pred P1;\n\t" \
            "W_%=:\n\t" \
            "mbarrier.try_wait.parity.acquire.cta.shared::cta.b64 P1, [%0], %1, 0x989680;\n\t" \
            "@P1 bra.uni D_%=;\n\t" \
            "bra.uni W_%=;\n\t" \
            "D_%=:\n\t}" :: "r"(_m), "r"(_p) : "memory"); \
    } } while (0)

#define TC_ALLOC(sa, n) \
    asm volatile("tcgen05.alloc.cta_group::1.sync.aligned.shared::cta.b32 [%0], %1;" \
        :: "r"(sa), "r"(n) : "memory")
#define TC_RELINQ() \
    asm volatile("tcgen05.relinquish_alloc_permit.cta_group::1.sync.aligned;")
#define TC_DEALLOC(t, n) \
    asm volatile("tcgen05.dealloc.cta_group::1.sync.aligned.b32 %0, %1;" :: "r"(t), "r"(n))
#define TC_COMMIT(mb) \
    asm volatile("tcgen05.commit.cta_group::1.mbarrier::arrive::one.shared::cluster.b64 [%0];" \
        :: "r"(mb) : "memory")
#define TC_FENCE_AFTER() asm volatile("tcgen05.fence::after_thread_sync;" ::: "memory")
#define TC_WAIT_LD() asm volatile("tcgen05.wait::ld.sync.aligned;" ::: "memory")

#define TC_LD_X32(r, ta) \
    asm volatile("tcgen05.ld.sync.aligned.32x32b.x32.b32 " \
        "{%0, %1, %2, %3, %4, %5, %6, %7, %8, %9, %10, %11, %12, %13, %14, %15, " \
        "%16, %17, %18, %19, %20, %21, %22, %23, %24, %25, %26, %27, %28, %29, %30, %31}, [%32];" \
        : "=r"((r)[0]), "=r"((r)[1]), "=r"((r)[2]), "=r"((r)[3]), \
          "=r"((r)[4]), "=r"((r)[5]), "=r"((r)[6]), "=r"((r)[7]), \
          "=r"((r)[8]), "=r"((r)[9]), "=r"((r)[10]), "=r"((r)[11]), \
          "=r"((r)[12]), "=r"((r)[13]), "=r"((r)[14]), "=r"((r)[15]), \
          "=r"((r)[16]), "=r"((r)[17]), "=r"((r)[18]), "=r"((r)[19]), \
          "=r"((r)[20]), "=r"((r)[21]), "=r"((r)[22]), "=r"((r)[23]), \
          "=r"((r)[24]), "=r"((r)[25]), "=r"((r)[26]), "=r"((r)[27]), \
          "=r"((r)[28]), "=r"((r)[29]), "=r"((r)[30]), "=r"((r)[31]) \
        : "r"(ta))

static constexpr uint64_t DESC_BASE_SW128 =
    (2ull << 61) | (1ull << 46) | (64ull << 32) | (1ull << 16);
__device__ __forceinline__ uint64_t make_desc(uint32_t addr) {
    return DESC_BASE_SW128 | ((uint64_t)(addr >> 4) & 0x3FFF);
}

// idesc: dtype=F32, atype=BF16, btype=BF16, N=256, M=128
#define GT_IDESC ((1u << 4) | (1u << 7) | (1u << 10) | ((256u / 8) << 17) | ((128u / 16) << 24))

#if defined(__CUDA_ARCH_FEAT_SM103_ALL)
__device__ __forceinline__ void mma_f16_ss(uint32_t d, uint64_t ad, uint64_t bd,
                                           uint32_t idesc, bool acc) {
    uint32_t en = acc ? 1u : 0u;
    asm volatile(
        "{\n\t.reg .pred p;\n\t"
        "setp.ne.u32 p, %5, 0;\n\t"
        "tcgen05.mma.cta_group::1.kind::f16 [%0], %1, %2, %3, {%4, %4, %4, %4}, p;\n\t"
        "}"
        :: "r"(d), "l"(ad), "l"(bd), "r"(idesc), "r"(0u), "r"(en)
        : "memory");
}
#endif

// SMEM layout for GEMM kernel (dynamic)
#define GT_A_OFF 1024
#define GT_B_OFF 33792
#define GT_SMEM_TOTAL 99328

// ---------------- kernels ----------------

// weight prep: W[256,256] fp32 (row=k, col=n) -> chunk images [12][256 n][64 bf16] SW128
// chunk c: g=c/3 covers k in [64g,64g+64); role: c%3==2 -> lo, else hi. grid=12, block=256.
__global__ __launch_bounds__(256)
void prep_w_kernel(const float* __restrict__ W, __nv_bfloat16* __restrict__ dst) {
    int c = blockIdx.x, n = threadIdx.x;
    int g = c / 3, t = c % 3;
    char* base = (char*)dst + (size_t)c * 32768;
    #pragma unroll 4
    for (int j = 0; j < 64; j += 2) {
        float x0 = W[(size_t)(64 * g + j) * 256 + n];
        float x1 = W[(size_t)(64 * g + j + 1) * 256 + n];
        unsigned short h0 = (t == 2) ? f2bf_lo(x0) : f2bf(x0);
        unsigned short h1 = (t == 2) ? f2bf_lo(x1) : f2bf(x1);
        uint32_t off = n * 128 + j * 2;
        off ^= (off >> 3) & 0x70;
        *(uint32_t*)(base + off) = (uint32_t)h0 | ((uint32_t)h1 << 16);
    }
}

// C[M,256] = A[M,256] @ W[256,256]. grid: (M/128), block 256.
// sm_103a build: tcgen05 bf16x3 (uses prepped Wp). Plain sm_103 build: fp32 SIMT (uses Wf).
template <int EPI>
__global__ __launch_bounds__(256)
void gemm_tc_kernel(const float* __restrict__ A, const __nv_bfloat16* __restrict__ Wp,
                    const float* __restrict__ Wf,
                    const float* __restrict__ bias, float* __restrict__ C) {
#if defined(__CUDA_ARCH_FEAT_SM103_ALL)
    extern __shared__ char smem[];
    uint32_t sb = smem_u32(smem);
    int tid = threadIdx.x, wid = tid >> 5, lane = tid & 31;
    int tile = blockIdx.x;

    if (wid == 0) {
        TC_ALLOC(sb + 0, 256);
        TC_RELINQ();
    }
    if (tid == 0) { MBAR_INIT(sb + 16, 1); MBAR_INIT(sb + 24, 1); }
    __syncthreads();
    uint32_t tmem;
    asm volatile("ld.shared.b32 %0, [%1];" : "=r"(tmem) : "r"(sb + 0));

    int r = tid >> 1, jb = (tid & 1) * 32;
    const float* Arow = A + ((size_t)tile * 128 + r) * 256;
    int ph0 = 0, ph1 = 0;

    for (int c = 0; c < 12; c++) {
        int s = c & 1, g = c / 3, t = c % 3;
        if (c >= 2) {
            if (s == 0) { MBAR_WAIT(sb + 16, ph0); ph0 ^= 1; }
            else        { MBAR_WAIT(sb + 24, ph1); ph1 ^= 1; }
        }
        // B chunk: raw 32KB copy (pre-swizzled image)
        {
            const uint4* src = (const uint4*)((const char*)Wp + (size_t)c * 32768);
            uint4* dst = (uint4*)(smem + GT_B_OFF + s * 32768);
            #pragma unroll
            for (int i = 0; i < 8; i++) dst[tid + 256 * i] = src[tid + 256 * i];
        }
        // A chunk: fp32 -> hi/lo bf16, swizzled
        {
            const float* Ap = Arow + g * 64 + jb;
            char* As = smem + GT_A_OFF + s * 16384;
            #pragma unroll
            for (int j = 0; j < 32; j += 2) {
                float x0 = Ap[j], x1 = Ap[j + 1];
                unsigned short h0, h1;
                if (t == 1) { h0 = f2bf_lo(x0); h1 = f2bf_lo(x1); }
                else        { h0 = f2bf(x0);    h1 = f2bf(x1); }
                uint32_t off = r * 128 + (jb + j) * 2;
                off ^= (off >> 3) & 0x70;
                *(uint32_t*)(As + off) = (uint32_t)h0 | ((uint32_t)h1 << 16);
            }
        }
        asm volatile("fence.proxy.async.shared::cta;" ::: "memory");
        __syncthreads();
        if (wid == 0 && elect_one_pred()) {
            uint64_t ad = make_desc(sb + GT_A_OFF + s * 16384);
            uint64_t bd = make_desc(sb + GT_B_OFF + s * 32768);
            #pragma unroll
            for (int k = 0; k < 4; k++)
                mma_f16_ss(tmem, ad + k * 2, bd + k * 2, GT_IDESC, (c > 0) || (k > 0));
            TC_COMMIT(sb + 16 + s * 8);
        }
    }

    MBAR_WAIT(sb + 24, ph1);  // final commit (chunk 11) -> parity 1
    TC_FENCE_AFTER();
    __syncthreads();

    // epilogue: 8 passes of 32 cols, staged through SMEM for coalesced stores
    float* stage = (float*)(smem + GT_A_OFF);
    for (int p = 0; p < 8; p++) {
        if (wid < 4) {
            uint32_t regs[32];
            TC_LD_X32(regs, tmem + p * 32);
            TC_WAIT_LD();
            int row = wid * 32 + lane;
            #pragma unroll
            for (int j = 0; j < 32; j++) {
                float v = __uint_as_float(regs[j]);
                if (EPI >= 1) v += bias[p * 32 + j];
                if (EPI == 2) v = gelu_tanh(v);
                stage[row * 33 + j] = v;
            }
        }
        __syncthreads();
        #pragma unroll
        for (int i = 0; i < 16; i++) {
            int row = wid + 8 * i;
            C[((size_t)tile * 128 + row) * 256 + p * 32 + lane] = stage[row * 33 + lane];
        }
        __syncthreads();
    }

    if (tid == 0) { MBAR_INVAL(sb + 16); MBAR_INVAL(sb + 24); }
    __syncthreads();
    if (wid == 0) TC_DEALLOC(tmem, 256);
#else
    // -------- fp32 SIMT fallback (compiled for plain sm_103 targets) --------
    extern __shared__ char smem[];
    float* As = (float*)smem;               // [16][132] transposed
    float* Bs = (float*)(smem + 16 * 132 * 4);  // [16][64]
    int tid = threadIdx.x;
    int tile = blockIdx.x;
    int tx = tid & 15, ty = tid >> 4;          // tx: 4 cols, ty: 8 rows
    int ar = tid >> 1, ac = (tid & 1) * 8;     // A loads: 8 floats per thread
    int br = tid >> 4, bc = (tid & 15) * 4;    // B loads
    const float* Ag = A + ((size_t)tile * 128 + ar) * 256;

    for (int nb = 0; nb < 4; nb++) {
        float acc[8][4] = {};
        for (int k0 = 0; k0 < 256; k0 += 16) {
            float4 a0 = *(const float4*)&Ag[k0 + ac];
            float4 a1 = *(const float4*)&Ag[k0 + ac + 4];
            As[(ac + 0) * 132 + ar] = a0.x; As[(ac + 1) * 132 + ar] = a0.y;
            As[(ac + 2) * 132 + ar] = a0.z; As[(ac + 3) * 132 + ar] = a0.w;
            As[(ac + 4) * 132 + ar] = a1.x; As[(ac + 5) * 132 + ar] = a1.y;
            As[(ac + 6) * 132 + ar] = a1.z; As[(ac + 7) * 132 + ar] = a1.w;
            float4 bv = *(const float4*)&Wf[(size_t)(k0 + br) * 256 + nb * 64 + bc];
            *(float4*)&Bs[br * 64 + bc] = bv;
            __syncthreads();
            #pragma unroll
            for (int kk = 0; kk < 16; kk++) {
                float a[8], bb[4];
                #pragma unroll
                for (int i = 0; i < 8; i++) a[i] = As[kk * 132 + ty * 8 + i];
                float4 b4 = *(const float4*)&Bs[kk * 64 + tx * 4];
                bb[0] = b4.x; bb[1] = b4.y; bb[2] = b4.z; bb[3] = b4.w;
                #pragma unroll
                for (int i = 0; i < 8; i++)
                    #pragma unroll
                    for (int j = 0; j < 4; j++)
                        acc[i][j] += a[i] * bb[j];
            }
            __syncthreads();
        }
        #pragma unroll
        for (int i = 0; i < 8; i++) {
            size_t row = (size_t)tile * 128 + ty * 8 + i;
            int col = nb * 64 + tx * 4;
            float4 v;
            float* vp = &v.x;
            #pragma unroll
            for (int j = 0; j < 4; j++) {
                float u = acc[i][j];
                if (EPI >= 1) u += bias[col + j];
                if (EPI == 2) u = gelu_tanh(u);
                vp[j] = u;
            }
            *(float4*)&C[row * 256 + col] = v;
        }
    }
#endif
}

// out[b, r, :] = LN(emb[idx[r]] + upd[b, idx[r], :]) * sc + bi
__global__ __launch_bounds__(256)
void gather_ln_kernel(const float* __restrict__ emb, const float* __restrict__ upd,
                      const int* __restrict__ idx,
                      const float* __restrict__ sc, const float* __restrict__ bi,
                      float* __restrict__ out) {
    __shared__ float red[16];
    int r = blockIdx.x, b = blockIdx.y, t = threadIdx.x;
    int nrows = gridDim.x;
    int j = idx[r];
    float x = emb[(size_t)j * Dm + t] + upd[((size_t)b * NS + j) * Dm + t];
    float2 mv = block_meanrstd(x, red);
    out[((size_t)b * nrows + r) * Dm + t] = (x - mv.x) * mv.y * sc[t] + bi[t];
}

__global__ __launch_bounds__(256)
void row_ln_kernel(const float* __restrict__ in,
                   const float* __restrict__ sc, const float* __restrict__ bi,
                   float* __restrict__ out) {
    __shared__ float red[16];
    size_t row = (size_t)blockIdx.x * Dm;
    int t = threadIdx.x;
    float x = in[row + t];
    float2 mv = block_meanrstd(x, red);
    out[row + t] = (x - mv.x) * mv.y * sc[t] + bi[t];
}

// Fused masked attention (flash-style, fp32).
__global__ __launch_bounds__(256)
void attn_kernel(const float* __restrict__ Qg_, const float* __restrict__ Kg_,
                 const float* __restrict__ Vg_, const float* __restrict__ mask,
                 float* __restrict__ ctx) {
    const int TQ = 64, TK = 64;
    __shared__ float Qs[TQ][DH + 2];
    __shared__ float Ks[TK][DH + 2];
    __shared__ float Vs[TK][DH + 2];
    int qt = blockIdx.x, h = blockIdx.y, b = blockIdx.z;
    int tid = threadIdx.x, warp = tid >> 5, lane = tid & 31;

    const float* Qg = Qg_ + ((size_t)b * NQ + qt * TQ) * Dm + h * DH;
    for (int i = tid; i < TQ * 16; i += 256) {
        int r = i >> 4, c = (i & 15) * 4;
        float4 v = *(const float4*)&Qg[(size_t)r * Dm + c];
        Qs[r][c] = v.x; Qs[r][c + 1] = v.y; Qs[r][c + 2] = v.z; Qs[r][c + 3] = v.w;
    }

    float mrow[8], lrow[8], acc[8][2];
    #pragma unroll
    for (int r = 0; r < 8; r++) {
        mrow[r] = -1e30f; lrow[r] = 0.f; acc[r][0] = 0.f; acc[r][1] = 0.f;
    }
    __syncthreads();

    int qbase = qt * TQ + warp * 8;
    for (int k0 = 0; k0 < NK; k0 += TK) {
        const float* Kg = Kg_ + ((size_t)b * NK + k0) * Dm + h * DH;
        const float* Vg = Vg_ + ((size_t)b * NK + k0) * Dm + h * DH;
        for (int i = tid; i < TK * 16; i += 256) {
            int r = i >> 4, c = (i & 15) * 4;
            float4 kv = *(const float4*)&Kg[(size_t)r * Dm + c];
            Ks[r][c] = kv.x; Ks[r][c + 1] = kv.y; Ks[r][c + 2] = kv.z; Ks[r][c + 3] = kv.w;
            float4 vv = *(const float4*)&Vg[(size_t)r * Dm + c];
            Vs[r][c] = vv.x; Vs[r][c + 1] = vv.y; Vs[r][c + 2] = vv.z; Vs[r][c + 3] = vv.w;
        }
        __syncthreads();

        float s[8][2];
        #pragma unroll
        for (int r = 0; r < 8; r++) { s[r][0] = 0.f; s[r][1] = 0.f; }
        #pragma unroll
        for (int d = 0; d < DH; d += 2) {
            float2 ka = *(const float2*)&Ks[lane][d];
            float2 kb = *(const float2*)&Ks[lane + 32][d];
            #pragma unroll
            for (int r = 0; r < 8; r++) {
                float2 qv = *(const float2*)&Qs[warp * 8 + r][d];
                s[r][0] += qv.x * ka.x + qv.y * ka.y;
                s[r][1] += qv.x * kb.x + qv.y * kb.y;
            }
        }
        #pragma unroll
        for (int r = 0; r < 8; r++) {
            float m0 = mask[(size_t)(qbase + r) * NK + k0 + lane];
            float m1 = mask[(size_t)(qbase + r) * NK + k0 + lane + 32];
            s[r][0] = (m0 > 0.5f) ? s[r][0] * ATT_SCALE : -1e9f;
            s[r][1] = (m1 > 0.5f) ? s[r][1] * ATT_SCALE : -1e9f;
        }
        #pragma unroll
        for (int r = 0; r < 8; r++) {
            float mx = fmaxf(s[r][0], s[r][1]);
            #pragma unroll
            for (int o = 16; o > 0; o >>= 1)
                mx = fmaxf(mx, __shfl_xor_sync(0xffffffffu, mx, o));
            float mnew = fmaxf(mrow[r], mx);
            float alpha = __expf(mrow[r] - mnew);
            float p0 = __expf(s[r][0] - mnew);
            float p1 = __expf(s[r][1] - mnew);
            float ps = p0 + p1;
            #pragma unroll
            for (int o = 16; o > 0; o >>= 1)
                ps += __shfl_xor_sync(0xffffffffu, ps, o);
            lrow[r] = lrow[r] * alpha + ps;
            mrow[r] = mnew;
            acc[r][0] *= alpha; acc[r][1] *= alpha;
            s[r][0] = p0; s[r][1] = p1;
        }
        #pragma unroll 8
        for (int kk = 0; kk < 32; kk++) {
            float v0 = Vs[kk][lane];
            float v1 = Vs[kk][lane + 32];
            float v2 = Vs[kk + 32][lane];
            float v3 = Vs[kk + 32][lane + 32];
            #pragma unroll
            for (int r = 0; r < 8; r++) {
                float p0 = __shfl_sync(0xffffffffu, s[r][0], kk);
                float p1 = __shfl_sync(0xffffffffu, s[r][1], kk);
                acc[r][0] += p0 * v0 + p1 * v2;
                acc[r][1] += p0 * v1 + p1 * v3;
            }
        }
        __syncthreads();
    }
    #pragma unroll
    for (int r = 0; r < 8; r++) {
        float invl = 1.0f / lrow[r];
        size_t row = ((size_t)b * NQ + qbase + r) * Dm + h * DH;
        ctx[row + lane] = acc[r][0] * invl;
        ctx[row + lane + 32] = acc[r][1] * invl;
    }
}

// res = LN_eff( LN_outer(h + ffn) ); scatter-add into upd and out.
__global__ __launch_bounds__(256)
void final_scatter_kernel(const float* __restrict__ hbuf, const float* __restrict__ fbuf,
                          const int* __restrict__ idx,
                          const float* __restrict__ os, const float* __restrict__ ob,
                          const float* __restrict__ es, const float* __restrict__ eb,
                          float* __restrict__ upd, float* __restrict__ out) {
    __shared__ float red[16];
    int r = blockIdx.x, b = blockIdx.y, t = threadIdx.x;
    size_t row = ((size_t)b * NQ + r) * Dm;
    float x = hbuf[row + t] + fbuf[row + t];
    float2 mv = block_meanrstd(x, red);
    float y = (x - mv.x) * mv.y * os[t] + ob[t];
    float2 mv2 = block_meanrstd(y, red);
    float res = (y - mv2.x) * mv2.y * es[t] + eb[t];
    int j = idx[r];
    size_t o = ((size_t)b * NS + j) * Dm + t;
    atomicAdd(&upd[o], res);
    atomicAdd(&out[o], res);
}

// ---------------- host launcher ----------------
extern "C" void kernel_launch(void* const* d_in, const int* in_sizes, int n_in,
                              void* d_out, int out_size) {
    const float* update = (const float*)d_in[0];
    const float* emb    = (const float*)d_in[1];
    const float* mask   = (const float*)d_in[2];
    const float* Wq     = (const float*)d_in[3];
    const float* Wk     = (const float*)d_in[4];
    const float* Wv     = (const float*)d_in[5];
    const float* Wo     = (const float*)d_in[6];
    const float* W1     = (const float*)d_in[7];
    const float* b1     = (const float*)d_in[8];
    const float* W2     = (const float*)d_in[9];
    const float* b2     = (const float*)d_in[10];
    const float* sys_s  = (const float*)d_in[11];
    const float* sys_b  = (const float*)d_in[12];
    const float* eff_s  = (const float*)d_in[13];
    const float* eff_b  = (const float*)d_in[14];
    const float* in_s   = (const float*)d_in[15];
    const float* in_b   = (const float*)d_in[16];
    const float* out_s  = (const float*)d_in[17];
    const float* out_b  = (const float*)d_in[18];
    const int*   qidx   = (const int*)d_in[19];
    const int*   kidx   = (const int*)d_in[20];
    float* out = (float*)d_out;

    float *p_upd, *p_qn, *p_kn, *p_Q, *p_K, *p_V, *p_ctx, *p_h, *p_t, *p_r;
    __nv_bfloat16* p_w;
    cudaGetSymbolAddress((void**)&p_upd, g_upd);
    cudaGetSymbolAddress((void**)&p_qn,  g_qn);
    cudaGetSymbolAddress((void**)&p_kn,  g_kn);
    cudaGetSymbolAddress((void**)&p_Q,   g_Q);
    cudaGetSymbolAddress((void**)&p_K,   g_K);
    cudaGetSymbolAddress((void**)&p_V,   g_V);
    cudaGetSymbolAddress((void**)&p_ctx, g_ctx);
    cudaGetSymbolAddress((void**)&p_h,   g_h);
    cudaGetSymbolAddress((void**)&p_t,   g_t);
    cudaGetSymbolAddress((void**)&p_r,   g_r);
    cudaGetSymbolAddress((void**)&p_w,   g_wprep);

    cudaFuncSetAttribute(gemm_tc_kernel<0>, cudaFuncAttributeMaxDynamicSharedMemorySize, GT_SMEM_TOTAL);
    cudaFuncSetAttribute(gemm_tc_kernel<1>, cudaFuncAttributeMaxDynamicSharedMemorySize, GT_SMEM_TOTAL);
    cudaFuncSetAttribute(gemm_tc_kernel<2>, cudaFuncAttributeMaxDynamicSharedMemorySize, GT_SMEM_TOTAL);

    const size_t WCH = (size_t)12 * 256 * 64;  // bf16 elems per weight image
    prep_w_kernel<<<12, 256>>>(Wq, p_w + 0 * WCH);
    prep_w_kernel<<<12, 256>>>(Wk, p_w + 1 * WCH);
    prep_w_kernel<<<12, 256>>>(Wv, p_w + 2 * WCH);
    prep_w_kernel<<<12, 256>>>(Wo, p_w + 3 * WCH);
    prep_w_kernel<<<12, 256>>>(W1, p_w + 4 * WCH);
    prep_w_kernel<<<12, 256>>>(W2, p_w + 5 * WCH);

    cudaMemsetAsync(d_out, 0, (size_t)out_size * sizeof(float), 0);
    cudaMemcpyAsync(p_upd, update, (size_t)Bz * NS * Dm * sizeof(float),
                    cudaMemcpyDeviceToDevice, 0);

    for (int l = 0; l < Ll; l++) {
        const int* qi = qidx + l * NQ;
        const int* ki = kidx + l * NK;
        const float* mk = mask + (size_t)l * NQ * NK;

        gather_ln_kernel<<<dim3(NQ, Bz), 256>>>(emb, p_upd, qi, sys_s, sys_b, p_qn);
        gather_ln_kernel<<<dim3(NK, Bz), 256>>>(emb, p_upd, ki, sys_s, sys_b, p_kn);

        gemm_tc_kernel<0><<<(Bz * NQ) / 128, 256, GT_SMEM_TOTAL>>>(p_qn, p_w + 0 * WCH, Wq, nullptr, p_Q);
        gemm_tc_kernel<0><<<(Bz * NK) / 128, 256, GT_SMEM_TOTAL>>>(p_kn, p_w + 1 * WCH, Wk, nullptr, p_K);
        gemm_tc_kernel<0><<<(Bz * NK) / 128, 256, GT_SMEM_TOTAL>>>(p_kn, p_w + 2 * WCH, Wv, nullptr, p_V);

        attn_kernel<<<dim3(NQ / 64, Hh, Bz), 256>>>(p_Q, p_K, p_V, mk, p_ctx);

        gemm_tc_kernel<0><<<(Bz * NQ) / 128, 256, GT_SMEM_TOTAL>>>(p_ctx, p_w + 3 * WCH, Wo, nullptr, p_t);
        row_ln_kernel<<<Bz * NQ, 256>>>(p_t, in_s, in_b, p_h);

        gemm_tc_kernel<2><<<(Bz * NQ) / 128, 256, GT_SMEM_TOTAL>>>(p_h, p_w + 4 * WCH, W1, b1, p_t);
        gemm_tc_kernel<1><<<(Bz * NQ) / 128, 256, GT_SMEM_TOTAL>>>(p_t, p_w + 5 * WCH, W2, b2, p_r);

        final_scatter_kernel<<<dim3(NQ, Bz), 256>>>(p_h, p_r, qi,
                                                    out_s, out_b, eff_s, eff_b,
                                                    p_upd, out);
    }
}

// round 6
// speedup vs baseline: 1.1973x; 1.1973x over previous
#include <cuda_runtime.h>
#include <cuda_bf16.h>
#include <math.h>
#include <stdint.h>

#define Bz 32
#define NS 4096
#define Dm 256
#define Hh 4
#define DH 64
#define Ll 6
#define NQ 512
#define NK 1024
#define ATT_SCALE 0.125f

// ---------------- scratch (device globals; no allocation allowed) ----------------
__device__ float g_upd[(size_t)Bz * NS * Dm];   // running update_tensor state
__device__ float g_qn [(size_t)Bz * NQ * Dm];
__device__ float g_kn [(size_t)Bz * NK * Dm];
__device__ float g_Q  [(size_t)Bz * NQ * Dm];
__device__ float g_K  [(size_t)Bz * NK * Dm];
__device__ float g_V  [(size_t)Bz * NK * Dm];
__device__ float g_ctx[(size_t)Bz * NQ * Dm];
__device__ float g_h  [(size_t)Bz * NQ * Dm];
__device__ float g_t  [(size_t)Bz * NQ * Dm];
__device__ float g_r  [(size_t)Bz * NQ * Dm];
__device__ uint32_t g_mbits[(size_t)Ll * NQ * (NK / 32)];  // mask bitwords

// ---------------- small helpers ----------------
__device__ __forceinline__ uint32_t smem_u32(const void* p) {
    uint32_t a;
    asm("{ .reg .u64 t; cvta.to.shared.u64 t, %1; cvt.u32.u64 %0, t; }" : "=r"(a) : "l"(p));
    return a;
}
__device__ __forceinline__ uint32_t elect_one_pred() {
    uint32_t pred;
    asm volatile(
        "{\n\t.reg .pred p;\n\telect.sync _|p, 0xFFFFFFFF;\n\tselp.b32 %0, 1, 0, p;\n\t}"
        : "=r"(pred));
    return pred;
}
__device__ __forceinline__ unsigned short f2bf(float x) {
    __nv_bfloat16 b = __float2bfloat16_rn(x);
    return *reinterpret_cast<unsigned short*>(&b);
}
__device__ __forceinline__ unsigned short f2bf_lo(float x) {
    __nv_bfloat16 b = __float2bfloat16_rn(x);
    float hi = __bfloat162float(b);
    __nv_bfloat16 l = __float2bfloat16_rn(x - hi);
    return *reinterpret_cast<unsigned short*>(&l);
}
__device__ __forceinline__ uint32_t pack2(unsigned short a, unsigned short b) {
    return (uint32_t)a | ((uint32_t)b << 16);
}

__device__ __forceinline__ float2 block_meanrstd(float x, float* red) {
    float s1 = x, s2 = x * x;
    #pragma unroll
    for (int o = 16; o > 0; o >>= 1) {
        s1 += __shfl_xor_sync(0xffffffffu, s1, o);
        s2 += __shfl_xor_sync(0xffffffffu, s2, o);
    }
    int w = threadIdx.x >> 5, ln = threadIdx.x & 31;
    if (ln == 0) { red[w] = s1; red[8 + w] = s2; }
    __syncthreads();
    float m = 0.f, q = 0.f;
    #pragma unroll
    for (int i = 0; i < 8; i++) { m += red[i]; q += red[8 + i]; }
    __syncthreads();
    m *= (1.0f / Dm);
    q = q * (1.0f / Dm) - m * m;
    return make_float2(m, rsqrtf(fmaxf(q, 0.f) + 1e-5f));
}

__device__ __forceinline__ float gelu_tanh(float x) {
    const float c = 0.7978845608028654f;
    float t = tanhf(c * (x + 0.044715f * x * x * x));
    return 0.5f * x * (1.0f + t);
}

// ---------------- tcgen05 plumbing ----------------
#define MBAR_INIT(addr, cnt) \
    asm volatile("mbarrier.init.shared.b64 [%0], %1;" :: "r"(addr), "r"(cnt) : "memory")
#define MBAR_INVAL(addr) \
    asm volatile("mbarrier.inval.shared.b64 [%0];" :: "r"(addr) : "memory")
#define MBAR_WAIT(addr, par) do { \
    uint32_t _m = (addr); uint32_t _p = (par); uint32_t _d; \
    asm volatile("{\n\t.reg .pred p;\n\t" \
        "mbarrier.try_wait.parity.acquire.cta.shared::cta.b64 p, [%1], %2;\n\t" \
        "selp.b32 %0, 1, 0, p;\n\t}" : "=r"(_d) : "r"(_m), "r"(_p) : "memory"); \
    if (!_d) { \
        asm volatile("{\n\t.reg .pred P1;\n\t" \
            "W_%=:\n\t" \
            "mbarrier.try_wait.parity.acquire.cta.shared::cta.b64 P1, [%0], %1, 0x989680;\n\t" \
            "@P1 bra.uni D_%=;\n\t" \
            "bra.uni W_%=;\n\t" \
            "D_%=:\n\t}" :: "r"(_m), "r"(_p) : "memory"); \
    } } while (0)

#if defined(__CUDA_ARCH_FEAT_SM103_ALL)
#define TC_ALLOC(sa, n) \
    asm volatile("tcgen05.alloc.cta_group::1.sync.aligned.shared::cta.b32 [%0], %1;" \
        :: "r"(sa), "r"(n) : "memory")
#define TC_RELINQ() \
    asm volatile("tcgen05.relinquish_alloc_permit.cta_group::1.sync.aligned;")
#define TC_DEALLOC(t, n) \
    asm volatile("tcgen05.dealloc.cta_group::1.sync.aligned.b32 %0, %1;" :: "r"(t), "r"(n))
#define TC_COMMIT(mb) \
    asm volatile("tcgen05.commit.cta_group::1.mbarrier::arrive::one.shared::cluster.b64 [%0];" \
        :: "r"(mb) : "memory")
#define TC_FENCE_AFTER() asm volatile("tcgen05.fence::after_thread_sync;" ::: "memory")
#define TC_FENCE_BEFORE() asm volatile("tcgen05.fence::before_thread_sync;" ::: "memory")
#define TC_WAIT_LD() asm volatile("tcgen05.wait::ld.sync.aligned;" ::: "memory")
#define TC_WAIT_ST() asm volatile("tcgen05.wait::st.sync.aligned;" ::: "memory")

#define TC_LD_X32(r, ta) \
    asm volatile("tcgen05.ld.sync.aligned.32x32b.x32.b32 " \
        "{%0, %1, %2, %3, %4, %5, %6, %7, %8, %9, %10, %11, %12, %13, %14, %15, " \
        "%16, %17, %18, %19, %20, %21, %22, %23, %24, %25, %26, %27, %28, %29, %30, %31}, [%32];" \
        : "=r"((r)[0]), "=r"((r)[1]), "=r"((r)[2]), "=r"((r)[3]), \
          "=r"((r)[4]), "=r"((r)[5]), "=r"((r)[6]), "=r"((r)[7]), \
          "=r"((r)[8]), "=r"((r)[9]), "=r"((r)[10]), "=r"((r)[11]), \
          "=r"((r)[12]), "=r"((r)[13]), "=r"((r)[14]), "=r"((r)[15]), \
          "=r"((r)[16]), "=r"((r)[17]), "=r"((r)[18]), "=r"((r)[19]), \
          "=r"((r)[20]), "=r"((r)[21]), "=r"((r)[22]), "=r"((r)[23]), \
          "=r"((r)[24]), "=r"((r)[25]), "=r"((r)[26]), "=r"((r)[27]), \
          "=r"((r)[28]), "=r"((r)[29]), "=r"((r)[30]), "=r"((r)[31]) \
        : "r"(ta))

#define TC_ST_X32(ta, r) \
    asm volatile("tcgen05.st.sync.aligned.32x32b.x32.b32 [%0], " \
        "{%1, %2, %3, %4, %5, %6, %7, %8, %9, %10, %11, %12, %13, %14, %15, %16, " \
        "%17, %18, %19, %20, %21, %22, %23, %24, %25, %26, %27, %28, %29, %30, %31, %32};" \
        :: "r"(ta), \
           "r"((r)[0]), "r"((r)[1]), "r"((r)[2]), "r"((r)[3]), \
           "r"((r)[4]), "r"((r)[5]), "r"((r)[6]), "r"((r)[7]), \
           "r"((r)[8]), "r"((r)[9]), "r"((r)[10]), "r"((r)[11]), \
           "r"((r)[12]), "r"((r)[13]), "r"((r)[14]), "r"((r)[15]), \
           "r"((r)[16]), "r"((r)[17]), "r"((r)[18]), "r"((r)[19]), \
           "r"((r)[20]), "r"((r)[21]), "r"((r)[22]), "r"((r)[23]), \
           "r"((r)[24]), "r"((r)[25]), "r"((r)[26]), "r"((r)[27]), \
           "r"((r)[28]), "r"((r)[29]), "r"((r)[30]), "r"((r)[31]) \
        : "memory")
#endif

static constexpr uint64_t DESC_BASE_SW128 =
    (2ull << 61) | (1ull << 46) | (64ull << 32) | (1ull << 16);
__device__ __forceinline__ uint64_t make_desc(uint32_t addr) {
    return DESC_BASE_SW128 | ((uint64_t)(addr >> 4) & 0x3FFF);
}

// idesc (kind::f16, bf16 in, f32 acc): bits validated against examples.
#define IDESC_N128 ((1u << 4) | (1u << 7) | (1u << 10) | ((128u / 8) << 17) | ((128u / 16) << 24))
#define IDESC_N64  ((1u << 4) | (1u << 7) | (1u << 10) | ((64u  / 8) << 17) | ((128u / 16) << 24))

#if defined(__CUDA_ARCH_FEAT_SM103_ALL)
__device__ __forceinline__ void mma_f16_ss(uint32_t d, uint64_t ad, uint64_t bd,
                                           uint32_t idesc, bool acc) {
    uint32_t en = acc ? 1u : 0u;
    asm volatile(
        "{\n\t.reg .pred p;\n\t"
        "setp.ne.u32 p, %5, 0;\n\t"
        "tcgen05.mma.cta_group::1.kind::f16 [%0], %1, %2, %3, {%4, %4, %4, %4}, p;\n\t"
        "}"
        :: "r"(d), "l"(ad), "l"(bd), "r"(idesc), "r"(0u), "r"(en)
        : "memory");
}
__device__ __forceinline__ void mma_f16_ts(uint32_t d, uint32_t a, uint64_t bd,
                                           uint32_t idesc, bool acc) {
    uint32_t en = acc ? 1u : 0u;
    asm volatile(
        "{\n\t.reg .pred p;\n\t"
        "setp.ne.u32 p, %5, 0;\n\t"
        "tcgen05.mma.cta_group::1.kind::f16 [%0], [%1], %2, %3, {%4, %4, %4, %4}, p;\n\t"
        "}"
        :: "r"(d), "r"(a), "l"(bd), "r"(idesc), "r"(0u), "r"(en)
        : "memory");
}
#endif

// ---------------- attention SMEM layout (dynamic) ----------------
#define AT_QHI   2048
#define AT_QLO   18432
#define AT_KHI   34816
#define AT_KLO   51200
#define AT_VHI_A 67584
#define AT_VHI_B 75776
#define AT_VLO_A 83968
#define AT_VLO_B 92160
#define AT_SMEM_TOTAL 100352

// ---------------- kernels ----------------

// mask -> bitwords. grid (NQ/8, L), block 256 (8 warps x 32 lanes).
__global__ __launch_bounds__(256)
void prep_mask_kernel(const float* __restrict__ mask, uint32_t* __restrict__ bits) {
    int w = threadIdx.x >> 5, l = threadIdx.x & 31;
    int r = blockIdx.x * 8 + w, lev = blockIdx.y;
    const float* row = mask + ((size_t)lev * NQ + r) * NK;
    uint32_t myword = 0;
    for (int j = 0; j < 32; j++) {
        float m = row[j * 32 + l];
        uint32_t bal = __ballot_sync(0xffffffffu, m > 0.5f);
        if (l == j) myword = bal;
    }
    bits[((size_t)lev * NQ + r) * 32 + l] = myword;
}

// out[b, r, :] = LN(emb[idx[r]] + upd[b, idx[r], :]) * sc + bi
__global__ __launch_bounds__(256)
void gather_ln_kernel(const float* __restrict__ emb, const float* __restrict__ upd,
                      const int* __restrict__ idx,
                      const float* __restrict__ sc, const float* __restrict__ bi,
                      float* __restrict__ out) {
    __shared__ float red[16];
    int r = blockIdx.x, b = blockIdx.y, t = threadIdx.x;
    int nrows = gridDim.x;
    int j = idx[r];
    float x = emb[(size_t)j * Dm + t] + upd[((size_t)b * NS + j) * Dm + t];
    float2 mv = block_meanrstd(x, red);
    out[((size_t)b * nrows + r) * Dm + t] = (x - mv.x) * mv.y * sc[t] + bi[t];
}

__global__ __launch_bounds__(256)
void row_ln_kernel(const float* __restrict__ in,
                   const float* __restrict__ sc, const float* __restrict__ bi,
                   float* __restrict__ out) {
    __shared__ float red[16];
    size_t row = (size_t)blockIdx.x * Dm;
    int t = threadIdx.x;
    float x = in[row + t];
    float2 mv = block_meanrstd(x, red);
    out[row + t] = (x - mv.x) * mv.y * sc[t] + bi[t];
}

// C[M,256] = A[M,256] @ W[256,256] (+bias)(+gelu)  -- proven R1 SIMT GEMM
// BM=64, BN=64, BK=16, 256 threads, 4x4 per thread. grid: (4, M/64)
template <int EPI>
__global__ __launch_bounds__(256)
void gemm_kernel(const float* __restrict__ A, const float* __restrict__ W,
                 const float* __restrict__ bias, float* __restrict__ C) {
    __shared__ float As[16][65];
    __shared__ float Bs[16][64];
    int bx = blockIdx.x, by = blockIdx.y;
    int tid = threadIdx.x;
    int tx = tid & 15, ty = tid >> 4;
    float acc[4][4] = {};
    int ar = tid >> 2, ac = (tid & 3) * 4;
    int br = tid >> 4, bc = (tid & 15) * 4;
    const float* Ag = A + ((size_t)by * 64 + ar) * 256;
    for (int k0 = 0; k0 < 256; k0 += 16) {
        float4 av = *(const float4*)&Ag[k0 + ac];
        As[ac + 0][ar] = av.x; As[ac + 1][ar] = av.y;
        As[ac + 2][ar] = av.z; As[ac + 3][ar] = av.w;
        float4 bv = *(const float4*)&W[(size_t)(k0 + br) * 256 + bx * 64 + bc];
        *(float4*)&Bs[br][bc] = bv;
        __syncthreads();
        #pragma unroll
        for (int kk = 0; kk < 16; kk++) {
            float a[4], bb[4];
            #pragma unroll
            for (int i = 0; i < 4; i++) a[i] = As[kk][ty * 4 + i];
            float4 b4 = *(const float4*)&Bs[kk][tx * 4];
            bb[0] = b4.x; bb[1] = b4.y; bb[2] = b4.z; bb[3] = b4.w;
            #pragma unroll
            for (int i = 0; i < 4; i++)
                #pragma unroll
                for (int jj = 0; jj < 4; jj++)
                    acc[i][jj] += a[i] * bb[jj];
        }
        __syncthreads();
    }
    #pragma unroll
    for (int i = 0; i < 4; i++) {
        size_t row = (size_t)by * 64 + ty * 4 + i;
        int col = bx * 64 + tx * 4;
        float4 v;
        float* vp = &v.x;
        #pragma unroll
        for (int jj = 0; jj < 4; jj++) {
            float u = acc[i][jj];
            if (EPI >= 1) u += bias[col + jj];
            if (EPI == 2) u = gelu_tanh(u);
            vp[jj] = u;
        }
        *(float4*)&C[row * 256 + col] = v;
    }
}

// ---------------- tcgen05 flash attention ----------------
// grid: (NQ/128, H, B), 256 threads.
// sm_103a: tensor-core bf16x3 flash. plain sm_103: fp32 SIMT flash fallback.
__global__ __launch_bounds__(256, 2)
void attn_tc_kernel(const float* __restrict__ Qg_, const float* __restrict__ Kg_,
                    const float* __restrict__ Vg_, const uint32_t* __restrict__ mbits,
                    float* __restrict__ ctx) {
    extern __shared__ char smem[];
    int qt = blockIdx.x, h = blockIdx.y, b = blockIdx.z;
    int tid = threadIdx.x, wid = tid >> 5, lane = tid & 31;
#if defined(__CUDA_ARCH_FEAT_SM103_ALL)
    uint32_t sb = smem_u32(smem);
    int sp = wid & 3, hf = wid >> 2;          // subpartition, column half
    float* redA = (float*)(smem + 64);        // [128]
    float* redB = (float*)(smem + 64 + 512);  // [128]

    if (wid == 0) { TC_ALLOC(sb + 0, 256); TC_RELINQ(); }
    if (tid == 0) { MBAR_INIT(sb + 16, 1); MBAR_INIT(sb + 24, 1); }
    __syncthreads();
    uint32_t tmem;
    asm volatile("ld.shared.b32 %0, [%1];" : "=r"(tmem) : "r"(sb + 0));

    // ---- load Q tile [128 x 64] -> qhi/qlo bf16 SW128 tiles ----
    {
        int r = tid >> 1, dbase = (tid & 1) * 32;
        const float* Qg = Qg_ + ((size_t)b * NQ + qt * 128 + r) * Dm + h * DH + dbase;
        char* hiT = smem + AT_QHI;
        char* loT = smem + AT_QLO;
        #pragma unroll
        for (int j = 0; j < 32; j += 2) {
            float x0 = Qg[j], x1 = Qg[j + 1];
            uint32_t off = r * 128 + (dbase + j) * 2;
            off ^= (off >> 3) & 0x70;
            *(uint32_t*)(hiT + off) = pack2(f2bf(x0), f2bf(x1));
            *(uint32_t*)(loT + off) = pack2(f2bf_lo(x0), f2bf_lo(x1));
        }
    }

    int qrow = sp * 32 + lane;  // this thread's q-row within the tile
    const uint32_t* rowbits = mbits + (size_t)(qt * 128 + qrow) * 32 + hf * 2;
    float mrow = -1e30f, lrow = 0.f;
    float acc[32];
    #pragma unroll
    for (int j = 0; j < 32; j++) acc[j] = 0.f;

    int ph1 = 0, ph2 = 0;
    uint32_t woff = (uint32_t)sp << 21;

    for (int t = 0; t < 8; t++) {
        int k0 = t * 128;
        // ---- load K,V tiles, convert ----
        {
            int r = tid >> 1, dbase = (tid & 1) * 32;
            const float* Kg = Kg_ + ((size_t)b * NK + k0 + r) * Dm + h * DH + dbase;
            const float* Vg = Vg_ + ((size_t)b * NK + k0 + r) * Dm + h * DH + dbase;
            char* khiT = smem + AT_KHI;
            char* kloT = smem + AT_KLO;
            #pragma unroll
            for (int j = 0; j < 32; j += 2) {
                float x0 = Kg[j], x1 = Kg[j + 1];
                uint32_t off = r * 128 + (dbase + j) * 2;
                off ^= (off >> 3) & 0x70;
                *(uint32_t*)(khiT + off) = pack2(f2bf(x0), f2bf(x1));
                *(uint32_t*)(kloT + off) = pack2(f2bf_lo(x0), f2bf_lo(x1));
            }
            // V transposed: tiles [64 d rows x 64 kv cols]
            int col = r & 63;
            char* vhiT = smem + (r < 64 ? AT_VHI_A : AT_VHI_B);
            char* vloT = smem + (r < 64 ? AT_VLO_A : AT_VLO_B);
            #pragma unroll
            for (int j = 0; j < 32; j++) {
                float x = Vg[j];
                uint32_t off = (dbase + j) * 128 + col * 2;
                off ^= (off >> 3) & 0x70;
                *(unsigned short*)(vhiT + off) = f2bf(x);
                *(unsigned short*)(vloT + off) = f2bf_lo(x);
            }
        }
        asm volatile("fence.proxy.async.shared::cta;" ::: "memory");
        __syncthreads();

        // ---- MMA1: S = Q K^T (3-term bf16) ----
        if (wid == 0 && elect_one_pred()) {
            uint64_t qhiD = make_desc(sb + AT_QHI);
            uint64_t qloD = make_desc(sb + AT_QLO);
            uint64_t khiD = make_desc(sb + AT_KHI);
            uint64_t kloD = make_desc(sb + AT_KLO);
            bool first = true;
            #pragma unroll
            for (int k = 0; k < 4; k++) { mma_f16_ss(tmem, qhiD + 2 * k, khiD + 2 * k, IDESC_N128, !first); first = false; }
            #pragma unroll
            for (int k = 0; k < 4; k++) mma_f16_ss(tmem, qloD + 2 * k, khiD + 2 * k, IDESC_N128, true);
            #pragma unroll
            for (int k = 0; k < 4; k++) mma_f16_ss(tmem, qhiD + 2 * k, kloD + 2 * k, IDESC_N128, true);
            TC_COMMIT(sb + 16);
        }
        MBAR_WAIT(sb + 16, ph1); ph1 ^= 1;
        TC_FENCE_AFTER();

        // ---- read S, mask+scale ----
        uint32_t sr[32];
        float s[64];
        TC_LD_X32(sr, tmem + hf * 64);
        TC_WAIT_LD();
        uint32_t w0 = rowbits[(k0 >> 5)];
        #pragma unroll
        for (int j = 0; j < 32; j++)
            s[j] = ((w0 >> j) & 1u) ? __uint_as_float(sr[j]) * ATT_SCALE : -1e9f;
        TC_LD_X32(sr, tmem + hf * 64 + 32);
        TC_WAIT_LD();
        uint32_t w1 = rowbits[(k0 >> 5) + 1];
        #pragma unroll
        for (int j = 0; j < 32; j++)
            s[32 + j] = ((w1 >> j) & 1u) ? __uint_as_float(sr[j]) * ATT_SCALE : -1e9f;

        // ---- online softmax ----
        float mloc = -1e30f;
        #pragma unroll
        for (int j = 0; j < 64; j++) mloc = fmaxf(mloc, s[j]);
        (hf ? redB : redA)[qrow] = mloc;
        __syncthreads();
        float mx = fmaxf(redA[qrow], redB[qrow]);
        float mnew = fmaxf(mrow, mx);
        float alpha = __expf(mrow - mnew);
        mrow = mnew;
        __syncthreads();
        float ps = 0.f;
        #pragma unroll
        for (int j = 0; j < 64; j++) {
            float p = __expf(s[j] - mnew);
            s[j] = p;
            ps += p;
        }
        (hf ? redB : redA)[qrow] = ps;
        __syncthreads();
        lrow = lrow * alpha + redA[qrow] + redB[qrow];

        // ---- P -> bf16 hi/lo into TMEM (overwrites S region) ----
        uint32_t pv[32];
        #pragma unroll
        for (int c = 0; c < 32; c++) pv[c] = pack2(f2bf(s[2 * c]), f2bf(s[2 * c + 1]));
        TC_ST_X32(tmem + hf * 32 + woff, pv);
        #pragma unroll
        for (int c = 0; c < 32; c++) pv[c] = pack2(f2bf_lo(s[2 * c]), f2bf_lo(s[2 * c + 1]));
        TC_ST_X32(tmem + 64 + hf * 32 + woff, pv);
        TC_WAIT_ST();
        TC_FENCE_BEFORE();
        __syncthreads();

        // ---- MMA2: Dtmp = P V (3-term, TS mode) ----
        if (wid == 0 && elect_one_pred()) {
            TC_FENCE_AFTER();
            uint64_t vhiA = make_desc(sb + AT_VHI_A);
            uint64_t vhiB = make_desc(sb + AT_VHI_B);
            uint64_t vloA = make_desc(sb + AT_VLO_A);
            uint64_t vloB = make_desc(sb + AT_VLO_B);
            bool first = true;
            #pragma unroll
            for (int s8 = 0; s8 < 8; s8++) {
                uint64_t bd = (s8 < 4 ? vhiA + 2 * s8 : vhiB + 2 * (s8 - 4));
                mma_f16_ts(tmem + 128, tmem + 0 + s8 * 8, bd, IDESC_N64, !first);
                first = false;
            }
            #pragma unroll
            for (int s8 = 0; s8 < 8; s8++) {
                uint64_t bd = (s8 < 4 ? vhiA + 2 * s8 : vhiB + 2 * (s8 - 4));
                mma_f16_ts(tmem + 128, tmem + 64 + s8 * 8, bd, IDESC_N64, true);
            }
            #pragma unroll
            for (int s8 = 0; s8 < 8; s8++) {
                uint64_t bd = (s8 < 4 ? vloA + 2 * s8 : vloB + 2 * (s8 - 4));
                mma_f16_ts(tmem + 128, tmem + 0 + s8 * 8, bd, IDESC_N64, true);
            }
            TC_COMMIT(sb + 24);
        }
        MBAR_WAIT(sb + 24, ph2); ph2 ^= 1;
        TC_FENCE_AFTER();

        // ---- accumulate ctx in registers ----
        uint32_t dr[32];
        TC_LD_X32(dr, tmem + 128 + hf * 32);
        TC_WAIT_LD();
        TC_FENCE_BEFORE();
        #pragma unroll
        for (int j = 0; j < 32; j++)
            acc[j] = acc[j] * alpha + __uint_as_float(dr[j]);
    }

    // ---- output ----
    float invl = 1.0f / lrow;
    float* orow = ctx + ((size_t)b * NQ + qt * 128 + qrow) * Dm + h * DH + hf * 32;
    #pragma unroll
    for (int j = 0; j < 32; j += 4) {
        float4 v;
        v.x = acc[j] * invl; v.y = acc[j + 1] * invl;
        v.z = acc[j + 2] * invl; v.w = acc[j + 3] * invl;
        *(float4*)(orow + j) = v;
    }

    __syncthreads();
    if (tid == 0) { MBAR_INVAL(sb + 16); MBAR_INVAL(sb + 24); }
    __syncthreads();
    if (wid == 0) TC_DEALLOC(tmem, 256);
#else
    // ---- fp32 SIMT flash fallback (plain sm_103 compile pass) ----
    float* Qs = (float*)smem;              // [128][66]
    float* Ks = Qs + 128 * 66;             // [64][66]
    float* Vs = Ks + 64 * 66;              // [64][66]
    const float* Qg = Qg_ + ((size_t)b * NQ + qt * 128) * Dm + h * DH;
    for (int i = tid; i < 128 * 16; i += 256) {
        int r = i >> 4, c = (i & 15) * 4;
        float4 v = *(const float4*)&Qg[(size_t)r * Dm + c];
        Qs[r * 66 + c] = v.x; Qs[r * 66 + c + 1] = v.y;
        Qs[r * 66 + c + 2] = v.z; Qs[r * 66 + c + 3] = v.w;
    }
    float mrow[16], lrow[16], acc[16][2];
    #pragma unroll
    for (int r = 0; r < 16; r++) {
        mrow[r] = -1e30f; lrow[r] = 0.f; acc[r][0] = 0.f; acc[r][1] = 0.f;
    }
    __syncthreads();
    int qbase = qt * 128 + wid * 16;
    for (int k0 = 0; k0 < NK; k0 += 64) {
        const float* Kg = Kg_ + ((size_t)b * NK + k0) * Dm + h * DH;
        const float* Vg = Vg_ + ((size_t)b * NK + k0) * Dm + h * DH;
        for (int i = tid; i < 64 * 16; i += 256) {
            int r = i >> 4, c = (i & 15) * 4;
            float4 kv = *(const float4*)&Kg[(size_t)r * Dm + c];
            Ks[r * 66 + c] = kv.x; Ks[r * 66 + c + 1] = kv.y;
            Ks[r * 66 + c + 2] = kv.z; Ks[r * 66 + c + 3] = kv.w;
            float4 vv = *(const float4*)&Vg[(size_t)r * Dm + c];
            Vs[r * 66 + c] = vv.x; Vs[r * 66 + c + 1] = vv.y;
            Vs[r * 66 + c + 2] = vv.z; Vs[r * 66 + c + 3] = vv.w;
        }
        __syncthreads();
        float s[16][2];
        #pragma unroll
        for (int r = 0; r < 16; r++) { s[r][0] = 0.f; s[r][1] = 0.f; }
        for (int d = 0; d < DH; d += 2) {
            float2 ka = *(const float2*)&Ks[lane * 66 + d];
            float2 kb = *(const float2*)&Ks[(lane + 32) * 66 + d];
            #pragma unroll
            for (int r = 0; r < 16; r++) {
                float2 qv = *(const float2*)&Qs[(wid * 16 + r) * 66 + d];
                s[r][0] += qv.x * ka.x + qv.y * ka.y;
                s[r][1] += qv.x * kb.x + qv.y * kb.y;
            }
        }
        #pragma unroll
        for (int r = 0; r < 16; r++) {
            uint32_t wa = mbits[(size_t)(qbase + r) * 32 + ((k0 + lane) >> 5)];
            uint32_t wb = mbits[(size_t)(qbase + r) * 32 + ((k0 + lane + 32) >> 5)];
            s[r][0] = ((wa >> ((k0 + lane) & 31)) & 1u) ? s[r][0] * ATT_SCALE : -1e9f;
            s[r][1] = ((wb >> ((k0 + lane + 32) & 31)) & 1u) ? s[r][1] * ATT_SCALE : -1e9f;
        }
        #pragma unroll
        for (int r = 0; r < 16; r++) {
            float mx = fmaxf(s[r][0], s[r][1]);
            for (int o = 16; o > 0; o >>= 1)
                mx = fmaxf(mx, __shfl_xor_sync(0xffffffffu, mx, o));
            float mnew = fmaxf(mrow[r], mx);
            float alpha = __expf(mrow[r] - mnew);
            float p0 = __expf(s[r][0] - mnew);
            float p1 = __expf(s[r][1] - mnew);
            float psum = p0 + p1;
            for (int o = 16; o > 0; o >>= 1)
                psum += __shfl_xor_sync(0xffffffffu, psum, o);
            lrow[r] = lrow[r] * alpha + psum;
            mrow[r] = mnew;
            acc[r][0] *= alpha; acc[r][1] *= alpha;
            s[r][0] = p0; s[r][1] = p1;
        }
        for (int kk = 0; kk < 32; kk++) {
            float v0 = Vs[kk * 66 + lane];
            float v1 = Vs[kk * 66 + lane + 32];
            float v2 = Vs[(kk + 32) * 66 + lane];
            float v3 = Vs[(kk + 32) * 66 + lane + 32];
            #pragma unroll
            for (int r = 0; r < 16; r++) {
                float p0 = __shfl_sync(0xffffffffu, s[r][0], kk);
                float p1 = __shfl_sync(0xffffffffu, s[r][1], kk);
                acc[r][0] += p0 * v0 + p1 * v2;
                acc[r][1] += p0 * v1 + p1 * v3;
            }
        }
        __syncthreads();
    }
    #pragma unroll
    for (int r = 0; r < 16; r++) {
        float invl = 1.0f / lrow[r];
        size_t row = ((size_t)b * NQ + qbase + r) * Dm + h * DH;
        ctx[row + lane] = acc[r][0] * invl;
        ctx[row + lane + 32] = acc[r][1] * invl;
    }
#endif
}

// res = LN_eff( LN_outer(h + ffn) ); scatter-add into upd and out.
__global__ __launch_bounds__(256)
void final_scatter_kernel(const float* __restrict__ hbuf, const float* __restrict__ fbuf,
                          const int* __restrict__ idx,
                          const float* __restrict__ os, const float* __restrict__ ob,
                          const float* __restrict__ es, const float* __restrict__ eb,
                          float* __restrict__ upd, float* __restrict__ out) {
    __shared__ float red[16];
    int r = blockIdx.x, b = blockIdx.y, t = threadIdx.x;
    size_t row = ((size_t)b * NQ + r) * Dm;
    float x = hbuf[row + t] + fbuf[row + t];
    float2 mv = block_meanrstd(x, red);
    float y = (x - mv.x) * mv.y * os[t] + ob[t];
    float2 mv2 = block_meanrstd(y, red);
    float res = (y - mv2.x) * mv2.y * es[t] + eb[t];
    int j = idx[r];
    size_t o = ((size_t)b * NS + j) * Dm + t;
    atomicAdd(&upd[o], res);
    atomicAdd(&out[o], res);
}

// ---------------- host launcher ----------------
extern "C" void kernel_launch(void* const* d_in, const int* in_sizes, int n_in,
                              void* d_out, int out_size) {
    const float* update = (const float*)d_in[0];
    const float* emb    = (const float*)d_in[1];
    const float* mask   = (const float*)d_in[2];
    const float* Wq     = (const float*)d_in[3];
    const float* Wk     = (const float*)d_in[4];
    const float* Wv     = (const float*)d_in[5];
    const float* Wo     = (const float*)d_in[6];
    const float* W1     = (const float*)d_in[7];
    const float* b1     = (const float*)d_in[8];
    const float* W2     = (const float*)d_in[9];
    const float* b2     = (const float*)d_in[10];
    const float* sys_s  = (const float*)d_in[11];
    const float* sys_b  = (const float*)d_in[12];
    const float* eff_s  = (const float*)d_in[13];
    const float* eff_b  = (const float*)d_in[14];
    const float* in_s   = (const float*)d_in[15];
    const float* in_b   = (const float*)d_in[16];
    const float* out_s  = (const float*)d_in[17];
    const float* out_b  = (const float*)d_in[18];
    const int*   qidx   = (const int*)d_in[19];
    const int*   kidx   = (const int*)d_in[20];
    float* out = (float*)d_out;

    float *p_upd, *p_qn, *p_kn, *p_Q, *p_K, *p_V, *p_ctx, *p_h, *p_t, *p_r;
    uint32_t* p_mb;
    cudaGetSymbolAddress((void**)&p_upd, g_upd);
    cudaGetSymbolAddress((void**)&p_qn,  g_qn);
    cudaGetSymbolAddress((void**)&p_kn,  g_kn);
    cudaGetSymbolAddress((void**)&p_Q,   g_Q);
    cudaGetSymbolAddress((void**)&p_K,   g_K);
    cudaGetSymbolAddress((void**)&p_V,   g_V);
    cudaGetSymbolAddress((void**)&p_ctx, g_ctx);
    cudaGetSymbolAddress((void**)&p_h,   g_h);
    cudaGetSymbolAddress((void**)&p_t,   g_t);
    cudaGetSymbolAddress((void**)&p_r,   g_r);
    cudaGetSymbolAddress((void**)&p_mb,  g_mbits);

    cudaFuncSetAttribute(attn_tc_kernel, cudaFuncAttributeMaxDynamicSharedMemorySize,
                         AT_SMEM_TOTAL);

    prep_mask_kernel<<<dim3(NQ / 8, Ll), 256>>>(mask, p_mb);

    cudaMemsetAsync(d_out, 0, (size_t)out_size * sizeof(float), 0);
    cudaMemcpyAsync(p_upd, update, (size_t)Bz * NS * Dm * sizeof(float),
                    cudaMemcpyDeviceToDevice, 0);

    for (int l = 0; l < Ll; l++) {
        const int* qi = qidx + l * NQ;
        const int* ki = kidx + l * NK;
        const uint32_t* mb = p_mb + (size_t)l * NQ * (NK / 32);

        gather_ln_kernel<<<dim3(NQ, Bz), 256>>>(emb, p_upd, qi, sys_s, sys_b, p_qn);
        gather_ln_kernel<<<dim3(NK, Bz), 256>>>(emb, p_upd, ki, sys_s, sys_b, p_kn);

        gemm_kernel<0><<<dim3(4, (Bz * NQ) / 64), 256>>>(p_qn, Wq, nullptr, p_Q);
        gemm_kernel<0><<<dim3(4, (Bz * NK) / 64), 256>>>(p_kn, Wk, nullptr, p_K);
        gemm_kernel<0><<<dim3(4, (Bz * NK) / 64), 256>>>(p_kn, Wv, nullptr, p_V);

        attn_tc_kernel<<<dim3(NQ / 128, Hh, Bz), 256, AT_SMEM_TOTAL>>>(p_Q, p_K, p_V, mb, p_ctx);

        gemm_kernel<0><<<dim3(4, (Bz * NQ) / 64), 256>>>(p_ctx, Wo, nullptr, p_t);
        row_ln_kernel<<<Bz * NQ, 256>>>(p_t, in_s, in_b, p_h);

        gemm_kernel<2><<<dim3(4, (Bz * NQ) / 64), 256>>>(p_h, W1, b1, p_t);
        gemm_kernel<1><<<dim3(4, (Bz * NQ) / 64), 256>>>(p_t, W2, b2, p_r);

        final_scatter_kernel<<<dim3(NQ, Bz), 256>>>(p_h, p_r, qi,
                                                    out_s, out_b, eff_s, eff_b,
                                                    p_upd, out);
    }
}

// round 7
// speedup vs baseline: 2.8508x; 2.3811x over previous
#include <cuda_runtime.h>
#include <cuda_bf16.h>
#include <math.h>
#include <stdint.h>

#define Bz 32
#define NS 4096
#define Dm 256
#define Hh 4
#define DH 64
#define Ll 6
#define NQ 512
#define NK 1024
#define ATT_SCALE 0.125f

// ---------------- scratch (device globals; no allocation allowed) ----------------
__device__ float g_upd[(size_t)Bz * NS * Dm];
__device__ float g_h  [(size_t)Bz * NQ * Dm];
__device__ float g_wo [(size_t)Bz * NQ * Dm];
__device__ float g_r  [(size_t)Bz * NQ * Dm];
__device__ uint32_t g_mbits[(size_t)Ll * NQ * (NK / 32)];
// bf16 hi/lo swizzled tile images: [tile][g(4)][hilo(2)] x 16KB
__device__ unsigned char g_img_qn [(size_t)128 * 8 * 16384];
__device__ unsigned char g_img_kn [(size_t)256 * 8 * 16384];
__device__ unsigned char g_img_Q  [(size_t)128 * 8 * 16384];
__device__ unsigned char g_img_K  [(size_t)256 * 8 * 16384];
__device__ unsigned char g_img_ctx[(size_t)128 * 8 * 16384];
__device__ unsigned char g_img_h  [(size_t)128 * 8 * 16384];
__device__ unsigned char g_img_t  [(size_t)128 * 8 * 16384];
// V transposed images: [tile][h(4)][half(2)][hilo(2)] x 8KB
__device__ unsigned char g_img_Vt [(size_t)256 * 16 * 8192];
// prepped weights: 6 matrices x 12 chunks x 32KB (pre-swizzled B images)
__device__ __nv_bfloat16 g_wprep[(size_t)6 * 12 * 256 * 64];

__device__ __forceinline__ size_t img_off(int tile, int g, int hilo) {
    return (((size_t)tile * 4 + g) * 2 + hilo) << 14;
}
__device__ __forceinline__ size_t imgv_off(int tile, int h, int half, int hilo) {
    return ((((size_t)tile * 4 + h) * 2 + half) * 2 + hilo) << 13;
}

// ---------------- small helpers ----------------
__device__ __forceinline__ uint32_t smem_u32(const void* p) {
    uint32_t a;
    asm("{ .reg .u64 t; cvta.to.shared.u64 t, %1; cvt.u32.u64 %0, t; }" : "=r"(a) : "l"(p));
    return a;
}
__device__ __forceinline__ uint32_t elect_one_pred() {
    uint32_t pred;
    asm volatile(
        "{\n\t.reg .pred p;\n\telect.sync _|p, 0xFFFFFFFF;\n\tselp.b32 %0, 1, 0, p;\n\t}"
        : "=r"(pred));
    return pred;
}
__device__ __forceinline__ unsigned short f2bf(float x) {
    __nv_bfloat16 b = __float2bfloat16_rn(x);
    return *reinterpret_cast<unsigned short*>(&b);
}
__device__ __forceinline__ unsigned short f2bf_lo(float x) {
    __nv_bfloat16 b = __float2bfloat16_rn(x);
    float hi = __bfloat162float(b);
    __nv_bfloat16 l = __float2bfloat16_rn(x - hi);
    return *reinterpret_cast<unsigned short*>(&l);
}
__device__ __forceinline__ uint32_t pack2(unsigned short a, unsigned short b) {
    return (uint32_t)a | ((uint32_t)b << 16);
}

__device__ __forceinline__ float2 block_meanrstd(float x, float* red) {
    float s1 = x, s2 = x * x;
    #pragma unroll
    for (int o = 16; o > 0; o >>= 1) {
        s1 += __shfl_xor_sync(0xffffffffu, s1, o);
        s2 += __shfl_xor_sync(0xffffffffu, s2, o);
    }
    int w = threadIdx.x >> 5, ln = threadIdx.x & 31;
    if (ln == 0) { red[w] = s1; red[8 + w] = s2; }
    __syncthreads();
    float m = 0.f, q = 0.f;
    #pragma unroll
    for (int i = 0; i < 8; i++) { m += red[i]; q += red[8 + i]; }
    __syncthreads();
    m *= (1.0f / Dm);
    q = q * (1.0f / Dm) - m * m;
    return make_float2(m, rsqrtf(fmaxf(q, 0.f) + 1e-5f));
}

__device__ __forceinline__ float gelu_tanh(float x) {
    const float c = 0.7978845608028654f;
    float t = tanhf(c * (x + 0.044715f * x * x * x));
    return 0.5f * x * (1.0f + t);
}

// ---------------- tcgen05 plumbing ----------------
#define MBAR_INIT(addr, cnt) \
    asm volatile("mbarrier.init.shared.b64 [%0], %1;" :: "r"(addr), "r"(cnt) : "memory")
#define MBAR_INVAL(addr) \
    asm volatile("mbarrier.inval.shared.b64 [%0];" :: "r"(addr) : "memory")
#define MBAR_WAIT(addr, par) do { \
    uint32_t _m = (addr); uint32_t _p = (par); uint32_t _d; \
    asm volatile("{\n\t.reg .pred p;\n\t" \
        "mbarrier.try_wait.parity.acquire.cta.shared::cta.b64 p, [%1], %2;\n\t" \
        "selp.b32 %0, 1, 0, p;\n\t}" : "=r"(_d) : "r"(_m), "r"(_p) : "memory"); \
    if (!_d) { \
        asm volatile("{\n\t.reg .pred P1;\n\t" \
            "W_%=:\n\t" \
            "mbarrier.try_wait.parity.acquire.cta.shared::cta.b64 P1, [%0], %1, 0x989680;\n\t" \
            "@P1 bra.uni D_%=;\n\t" \
            "bra.uni W_%=;\n\t" \
            "D_%=:\n\t}" :: "r"(_m), "r"(_p) : "memory"); \
    } } while (0)

#if defined(__CUDA_ARCH_FEAT_SM103_ALL)
#define TC_ALLOC(sa, n) \
    asm volatile("tcgen05.alloc.cta_group::1.sync.aligned.shared::cta.b32 [%0], %1;" \
        :: "r"(sa), "r"(n) : "memory")
#define TC_RELINQ() \
    asm volatile("tcgen05.relinquish_alloc_permit.cta_group::1.sync.aligned;")
#define TC_DEALLOC(t, n) \
    asm volatile("tcgen05.dealloc.cta_group::1.sync.aligned.b32 %0, %1;" :: "r"(t), "r"(n))
#define TC_COMMIT(mb) \
    asm volatile("tcgen05.commit.cta_group::1.mbarrier::arrive::one.shared::cluster.b64 [%0];" \
        :: "r"(mb) : "memory")
#define TC_FENCE_AFTER() asm volatile("tcgen05.fence::after_thread_sync;" ::: "memory")
#define TC_FENCE_BEFORE() asm volatile("tcgen05.fence::before_thread_sync;" ::: "memory")
#define TC_WAIT_LD() asm volatile("tcgen05.wait::ld.sync.aligned;" ::: "memory")
#define TC_WAIT_ST() asm volatile("tcgen05.wait::st.sync.aligned;" ::: "memory")

#define TC_LD_X32(r, ta) \
    asm volatile("tcgen05.ld.sync.aligned.32x32b.x32.b32 " \
        "{%0, %1, %2, %3, %4, %5, %6, %7, %8, %9, %10, %11, %12, %13, %14, %15, " \
        "%16, %17, %18, %19, %20, %21, %22, %23, %24, %25, %26, %27, %28, %29, %30, %31}, [%32];" \
        : "=r"((r)[0]), "=r"((r)[1]), "=r"((r)[2]), "=r"((r)[3]), \
          "=r"((r)[4]), "=r"((r)[5]), "=r"((r)[6]), "=r"((r)[7]), \
          "=r"((r)[8]), "=r"((r)[9]), "=r"((r)[10]), "=r"((r)[11]), \
          "=r"((r)[12]), "=r"((r)[13]), "=r"((r)[14]), "=r"((r)[15]), \
          "=r"((r)[16]), "=r"((r)[17]), "=r"((r)[18]), "=r"((r)[19]), \
          "=r"((r)[20]), "=r"((r)[21]), "=r"((r)[22]), "=r"((r)[23]), \
          "=r"((r)[24]), "=r"((r)[25]), "=r"((r)[26]), "=r"((r)[27]), \
          "=r"((r)[28]), "=r"((r)[29]), "=r"((r)[30]), "=r"((r)[31]) \
        : "r"(ta))

#define TC_ST_X32(ta, r) \
    asm volatile("tcgen05.st.sync.aligned.32x32b.x32.b32 [%0], " \
        "{%1, %2, %3, %4, %5, %6, %7, %8, %9, %10, %11, %12, %13, %14, %15, %16, " \
        "%17, %18, %19, %20, %21, %22, %23, %24, %25, %26, %27, %28, %29, %30, %31, %32};" \
        :: "r"(ta), \
           "r"((r)[0]), "r"((r)[1]), "r"((r)[2]), "r"((r)[3]), \
           "r"((r)[4]), "r"((r)[5]), "r"((r)[6]), "r"((r)[7]), \
           "r"((r)[8]), "r"((r)[9]), "r"((r)[10]), "r"((r)[11]), \
           "r"((r)[12]), "r"((r)[13]), "r"((r)[14]), "r"((r)[15]), \
           "r"((r)[16]), "r"((r)[17]), "r"((r)[18]), "r"((r)[19]), \
           "r"((r)[20]), "r"((r)[21]), "r"((r)[22]), "r"((r)[23]), \
           "r"((r)[24]), "r"((r)[25]), "r"((r)[26]), "r"((r)[27]), \
           "r"((r)[28]), "r"((r)[29]), "r"((r)[30]), "r"((r)[31]) \
        : "memory")

__device__ __forceinline__ void mma_f16_ss(uint32_t d, uint64_t ad, uint64_t bd,
                                           uint32_t idesc, bool acc) {
    uint32_t en = acc ? 1u : 0u;
    asm volatile(
        "{\n\t.reg .pred p;\n\t"
        "setp.ne.u32 p, %5, 0;\n\t"
        "tcgen05.mma.cta_group::1.kind::f16 [%0], %1, %2, %3, {%4, %4, %4, %4}, p;\n\t"
        "}"
        :: "r"(d), "l"(ad), "l"(bd), "r"(idesc), "r"(0u), "r"(en)
        : "memory");
}
__device__ __forceinline__ void mma_f16_ts(uint32_t d, uint32_t a, uint64_t bd,
                                           uint32_t idesc, bool acc) {
    uint32_t en = acc ? 1u : 0u;
    asm volatile(
        "{\n\t.reg .pred p;\n\t"
        "setp.ne.u32 p, %5, 0;\n\t"
        "tcgen05.mma.cta_group::1.kind::f16 [%0], [%1], %2, %3, {%4, %4, %4, %4}, p;\n\t"
        "}"
        :: "r"(d), "r"(a), "l"(bd), "r"(idesc), "r"(0u), "r"(en)
        : "memory");
}
#endif

static constexpr uint64_t DESC_BASE_SW128 =
    (2ull << 61) | (1ull << 46) | (64ull << 32) | (1ull << 16);
__device__ __forceinline__ uint64_t make_desc(uint32_t addr) {
    return DESC_BASE_SW128 | ((uint64_t)(addr >> 4) & 0x3FFF);
}

#define IDESC_N256 ((1u << 4) | (1u << 7) | (1u << 10) | ((256u / 8) << 17) | ((128u / 16) << 24))
#define IDESC_N128 ((1u << 4) | (1u << 7) | (1u << 10) | ((128u / 8) << 17) | ((128u / 16) << 24))
#define IDESC_N64  ((1u << 4) | (1u << 7) | (1u << 10) | ((64u  / 8) << 17) | ((128u / 16) << 24))

// GEMM SMEM layout
#define GT_A_OFF 1024
#define GT_B_OFF 33792
#define GT_SMEM_TOTAL 99328
// attention SMEM layout
#define AT_QHI   2048
#define AT_QLO   18432
#define AT_KHI   34816
#define AT_KLO   51200
#define AT_VHI_A 67584
#define AT_VHI_B 75776
#define AT_VLO_A 83968
#define AT_VLO_B 92160
#define AT_SMEM_TOTAL 100352

// ---------------- prep: weights + mask bits, one launch ----------------
// grid = 72 + Ll*(NQ/8)/8... weights: 72 blocks; mask: Ll*64 blocks of 8 rows.
__global__ __launch_bounds__(256)
void prep_all_kernel(const float* __restrict__ Wq, const float* __restrict__ Wk,
                     const float* __restrict__ Wv, const float* __restrict__ Wo,
                     const float* __restrict__ W1, const float* __restrict__ W2,
                     __nv_bfloat16* __restrict__ wprep,
                     const float* __restrict__ mask, uint32_t* __restrict__ bits) {
    int bx = blockIdx.x;
    if (bx < 72) {
        int w = bx / 12, c = bx % 12;
        const float* W = (w == 0) ? Wq : (w == 1) ? Wk : (w == 2) ? Wv
                       : (w == 3) ? Wo : (w == 4) ? W1 : W2;
        int g = c / 3, t = c % 3, n = threadIdx.x;
        char* base = (char*)wprep + ((size_t)w * 12 + c) * 32768;
        #pragma unroll 4
        for (int j = 0; j < 64; j += 2) {
            float x0 = W[(size_t)(64 * g + j) * 256 + n];
            float x1 = W[(size_t)(64 * g + j + 1) * 256 + n];
            unsigned short h0 = (t == 2) ? f2bf_lo(x0) : f2bf(x0);
            unsigned short h1 = (t == 2) ? f2bf_lo(x1) : f2bf(x1);
            uint32_t off = n * 128 + j * 2;
            off ^= (off >> 3) & 0x70;
            *(uint32_t*)(base + off) = pack2(h0, h1);
        }
    } else {
        int idx = bx - 72;
        int lev = idx >> 6, rblk = idx & 63;
        int w = threadIdx.x >> 5, l = threadIdx.x & 31;
        int r = rblk * 8 + w;
        const float* row = mask + ((size_t)lev * NQ + r) * NK;
        uint32_t myword = 0;
        for (int j = 0; j < 32; j++) {
            uint32_t bal = __ballot_sync(0xffffffffu, row[j * 32 + l] > 0.5f);
            if (l == j) myword = bal;
        }
        bits[((size_t)lev * NQ + r) * 32 + l] = myword;
    }
}

// ---------------- gather + LN -> images ----------------
__global__ __launch_bounds__(256)
void gather_ln_img_kernel(const float* __restrict__ emb, const float* __restrict__ upd,
                          const int* __restrict__ idx,
                          const float* __restrict__ sc, const float* __restrict__ bi,
                          unsigned char* __restrict__ img, int nrows) {
    __shared__ float red[16];
    int r = blockIdx.x, b = blockIdx.y, t = threadIdx.x;
    int j = idx[r];
    float x = emb[(size_t)j * Dm + t] + upd[((size_t)b * NS + j) * Dm + t];
    float2 mv = block_meanrstd(x, red);
    float y = (x - mv.x) * mv.y * sc[t] + bi[t];
    int row = b * nrows + r;
    int tile = row >> 7, rr = row & 127;
    int g = t >> 6, c = t & 63;
    uint32_t off = rr * 128 + c * 2;
    off ^= (off >> 3) & 0x70;
    *(unsigned short*)(img + img_off(tile, g, 0) + off) = f2bf(y);
    *(unsigned short*)(img + img_off(tile, g, 1) + off) = f2bf_lo(y);
}

// row LN -> fp32 + images
__global__ __launch_bounds__(256)
void row_ln_img_kernel(const float* __restrict__ in,
                       const float* __restrict__ sc, const float* __restrict__ bi,
                       float* __restrict__ outf, unsigned char* __restrict__ img) {
    __shared__ float red[16];
    int row = blockIdx.x, t = threadIdx.x;
    float x = in[(size_t)row * Dm + t];
    float2 mv = block_meanrstd(x, red);
    float y = (x - mv.x) * mv.y * sc[t] + bi[t];
    outf[(size_t)row * Dm + t] = y;
    int tile = row >> 7, rr = row & 127;
    int g = t >> 6, c = t & 63;
    uint32_t off = rr * 128 + c * 2;
    off ^= (off >> 3) & 0x70;
    *(unsigned short*)(img + img_off(tile, g, 0) + off) = f2bf(y);
    *(unsigned short*)(img + img_off(tile, g, 1) + off) = f2bf_lo(y);
}

// ---------------- tc GEMM on images ----------------
// C[M,256] = A[M,256] @ W. A given as images; W as prepped chunks.
// OUT: 0=fp32 Cf, 1=images Cimg, 2=transposed V images Cimg.
template <int EPI, int OUT>
__global__ __launch_bounds__(256)
void gemm_img_kernel(const unsigned char* __restrict__ Aimg,
                     const __nv_bfloat16* __restrict__ Wp,
                     const float* __restrict__ bias,
                     float* __restrict__ Cf, unsigned char* __restrict__ Cimg) {
#if defined(__CUDA_ARCH_FEAT_SM103_ALL)
    extern __shared__ char smem[];
    uint32_t sb = smem_u32(smem);
    int tid = threadIdx.x, wid = tid >> 5, lane = tid & 31;
    int tile = blockIdx.x;

    if (wid == 0) { TC_ALLOC(sb + 0, 256); TC_RELINQ(); }
    if (tid == 0) { MBAR_INIT(sb + 16, 1); MBAR_INIT(sb + 24, 1); }
    __syncthreads();
    uint32_t tmem;
    asm volatile("ld.shared.b32 %0, [%1];" : "=r"(tmem) : "r"(sb + 0));

    int ph0 = 0, ph1 = 0;
    for (int c = 0; c < 12; c++) {
        int s = c & 1, g = c / 3, t = c % 3;
        if (c >= 2) {
            if (s == 0) { MBAR_WAIT(sb + 16, ph0); ph0 ^= 1; }
            else        { MBAR_WAIT(sb + 24, ph1); ph1 ^= 1; }
        }
        // A image chunk (16KB raw)
        {
            int aidx = tile * 8 + g * 2 + (t == 1 ? 1 : 0);
            const uint4* src = (const uint4*)(Aimg + ((size_t)aidx << 14));
            uint4* dst = (uint4*)(smem + GT_A_OFF + s * 16384);
            #pragma unroll
            for (int i = 0; i < 4; i++) dst[tid + 256 * i] = src[tid + 256 * i];
        }
        // B chunk (32KB raw)
        {
            const uint4* src = (const uint4*)((const char*)Wp + (size_t)c * 32768);
            uint4* dst = (uint4*)(smem + GT_B_OFF + s * 32768);
            #pragma unroll
            for (int i = 0; i < 8; i++) dst[tid + 256 * i] = src[tid + 256 * i];
        }
        asm volatile("fence.proxy.async.shared::cta;" ::: "memory");
        __syncthreads();
        if (wid == 0 && elect_one_pred()) {
            uint64_t ad = make_desc(sb + GT_A_OFF + s * 16384);
            uint64_t bd = make_desc(sb + GT_B_OFF + s * 32768);
            #pragma unroll
            for (int k = 0; k < 4; k++)
                mma_f16_ss(tmem, ad + k * 2, bd + k * 2, IDESC_N256, (c > 0) || (k > 0));
            TC_COMMIT(sb + 16 + s * 8);
        }
    }
    MBAR_WAIT(sb + 24, ph1);
    TC_FENCE_AFTER();
    __syncthreads();

    if (OUT == 0) {
        float* stage = (float*)(smem + GT_A_OFF);
        for (int p = 0; p < 8; p++) {
            if (wid < 4) {
                uint32_t regs[32];
                TC_LD_X32(regs, tmem + p * 32);
                TC_WAIT_LD();
                int row = wid * 32 + lane;
                #pragma unroll
                for (int j = 0; j < 32; j++) {
                    float v = __uint_as_float(regs[j]);
                    if (EPI >= 1) v += bias[p * 32 + j];
                    if (EPI == 2) v = gelu_tanh(v);
                    stage[row * 33 + j] = v;
                }
            }
            __syncthreads();
            #pragma unroll
            for (int i = 0; i < 16; i++) {
                int row = wid + 8 * i;
                Cf[((size_t)tile * 128 + row) * 256 + p * 32 + lane] = stage[row * 33 + lane];
            }
            __syncthreads();
        }
    } else {
        int sp = wid & 3, hf = wid >> 2;
        int rr = sp * 32 + lane;
        for (int p = hf * 4; p < hf * 4 + 4; p++) {
            uint32_t regs[32];
            TC_LD_X32(regs, tmem + p * 32);
            TC_WAIT_LD();
            float v[32];
            #pragma unroll
            for (int j = 0; j < 32; j++) {
                float u = __uint_as_float(regs[j]);
                if (EPI >= 1) u += bias[p * 32 + j];
                if (EPI == 2) u = gelu_tanh(u);
                v[j] = u;
            }
            if (OUT == 1) {
                unsigned char* hi = Cimg + img_off(tile, p >> 1, 0);
                unsigned char* lo = Cimg + img_off(tile, p >> 1, 1);
                int cb = (p & 1) * 32;
                #pragma unroll
                for (int j = 0; j < 32; j += 2) {
                    uint32_t off = rr * 128 + (cb + j) * 2;
                    off ^= (off >> 3) & 0x70;
                    *(uint32_t*)(hi + off) = pack2(f2bf(v[j]), f2bf(v[j + 1]));
                    *(uint32_t*)(lo + off) = pack2(f2bf_lo(v[j]), f2bf_lo(v[j + 1]));
                }
            } else {  // OUT == 2: V transposed images
                int kv = rr & 63, half = rr >> 6;
                unsigned char* hi = Cimg + imgv_off(tile, p >> 1, half, 0);
                unsigned char* lo = Cimg + imgv_off(tile, p >> 1, half, 1);
                #pragma unroll
                for (int j = 0; j < 32; j++) {
                    int dd = (p & 1) * 32 + j;
                    uint32_t off = dd * 128 + kv * 2;
                    off ^= (off >> 3) & 0x70;
                    *(unsigned short*)(hi + off) = f2bf(v[j]);
                    *(unsigned short*)(lo + off) = f2bf_lo(v[j]);
                }
            }
        }
    }

    __syncthreads();
    if (tid == 0) { MBAR_INVAL(sb + 16); MBAR_INVAL(sb + 24); }
    __syncthreads();
    if (wid == 0) TC_DEALLOC(tmem, 256);
#endif
}

// ---------------- tc flash attention on images ----------------
// grid: (NQ/128, H, B), 256 threads.
__global__ __launch_bounds__(256, 2)
void attn_tc_kernel(const unsigned char* __restrict__ Qimg,
                    const unsigned char* __restrict__ Kimg,
                    const unsigned char* __restrict__ Vimg,
                    const uint32_t* __restrict__ mbits,
                    unsigned char* __restrict__ ctxImg) {
#if defined(__CUDA_ARCH_FEAT_SM103_ALL)
    extern __shared__ char smem[];
    uint32_t sb = smem_u32(smem);
    int qt = blockIdx.x, h = blockIdx.y, b = blockIdx.z;
    int tid = threadIdx.x, wid = tid >> 5, lane = tid & 31;
    int sp = wid & 3, hf = wid >> 2;
    float* redA = (float*)(smem + 64);
    float* redB = (float*)(smem + 64 + 512);

    if (wid == 0) { TC_ALLOC(sb + 0, 256); TC_RELINQ(); }
    if (tid == 0) { MBAR_INIT(sb + 16, 1); MBAR_INIT(sb + 24, 1); }
    __syncthreads();
    uint32_t tmem;
    asm volatile("ld.shared.b32 %0, [%1];" : "=r"(tmem) : "r"(sb + 0));

    // Q tile images (raw copies, once)
    {
        const uint4* qh = (const uint4*)(Qimg + img_off(b * 4 + qt, h, 0));
        const uint4* ql = (const uint4*)(Qimg + img_off(b * 4 + qt, h, 1));
        uint4* dh = (uint4*)(smem + AT_QHI);
        uint4* dl = (uint4*)(smem + AT_QLO);
        #pragma unroll
        for (int i = 0; i < 4; i++) {
            dh[tid + 256 * i] = qh[tid + 256 * i];
            dl[tid + 256 * i] = ql[tid + 256 * i];
        }
    }

    int qrow = sp * 32 + lane;
    const uint32_t* rowbits = mbits + (size_t)(qt * 128 + qrow) * 32 + hf * 2;
    float mrow = -1e30f, lrow = 0.f;
    float acc[32];
    #pragma unroll
    for (int j = 0; j < 32; j++) acc[j] = 0.f;

    int ph1 = 0, ph2 = 0;
    uint32_t woff = (uint32_t)sp << 21;

    for (int t = 0; t < 8; t++) {
        int k0 = t * 128;
        // K + V^T tile images (raw copies)
        {
            int kt = b * 8 + t;
            const uint4* kh = (const uint4*)(Kimg + img_off(kt, h, 0));
            const uint4* kl = (const uint4*)(Kimg + img_off(kt, h, 1));
            uint4* dh = (uint4*)(smem + AT_KHI);
            uint4* dl = (uint4*)(smem + AT_KLO);
            #pragma unroll
            for (int i = 0; i < 4; i++) {
                dh[tid + 256 * i] = kh[tid + 256 * i];
                dl[tid + 256 * i] = kl[tid + 256 * i];
            }
            const uint4* vha = (const uint4*)(Vimg + imgv_off(kt, h, 0, 0));
            const uint4* vhb = (const uint4*)(Vimg + imgv_off(kt, h, 1, 0));
            const uint4* vla = (const uint4*)(Vimg + imgv_off(kt, h, 0, 1));
            const uint4* vlb = (const uint4*)(Vimg + imgv_off(kt, h, 1, 1));
            uint4* da = (uint4*)(smem + AT_VHI_A);
            uint4* db = (uint4*)(smem + AT_VHI_B);
            uint4* dc = (uint4*)(smem + AT_VLO_A);
            uint4* dd = (uint4*)(smem + AT_VLO_B);
            #pragma unroll
            for (int i = 0; i < 2; i++) {
                da[tid + 256 * i] = vha[tid + 256 * i];
                db[tid + 256 * i] = vhb[tid + 256 * i];
                dc[tid + 256 * i] = vla[tid + 256 * i];
                dd[tid + 256 * i] = vlb[tid + 256 * i];
            }
        }
        asm volatile("fence.proxy.async.shared::cta;" ::: "memory");
        __syncthreads();

        // MMA1: S = Q K^T (3-term)
        if (wid == 0 && elect_one_pred()) {
            uint64_t qhiD = make_desc(sb + AT_QHI);
            uint64_t qloD = make_desc(sb + AT_QLO);
            uint64_t khiD = make_desc(sb + AT_KHI);
            uint64_t kloD = make_desc(sb + AT_KLO);
            bool first = true;
            #pragma unroll
            for (int k = 0; k < 4; k++) { mma_f16_ss(tmem, qhiD + 2 * k, khiD + 2 * k, IDESC_N128, !first); first = false; }
            #pragma unroll
            for (int k = 0; k < 4; k++) mma_f16_ss(tmem, qloD + 2 * k, khiD + 2 * k, IDESC_N128, true);
            #pragma unroll
            for (int k = 0; k < 4; k++) mma_f16_ss(tmem, qhiD + 2 * k, kloD + 2 * k, IDESC_N128, true);
            TC_COMMIT(sb + 16);
        }
        MBAR_WAIT(sb + 16, ph1); ph1 ^= 1;
        TC_FENCE_AFTER();

        // read S, mask + scale
        uint32_t sr[32];
        float s[64];
        TC_LD_X32(sr, tmem + hf * 64);
        TC_WAIT_LD();
        uint32_t w0 = rowbits[(k0 >> 5)];
        #pragma unroll
        for (int j = 0; j < 32; j++)
            s[j] = ((w0 >> j) & 1u) ? __uint_as_float(sr[j]) * ATT_SCALE : -1e9f;
        TC_LD_X32(sr, tmem + hf * 64 + 32);
        TC_WAIT_LD();
        uint32_t w1 = rowbits[(k0 >> 5) + 1];
        #pragma unroll
        for (int j = 0; j < 32; j++)
            s[32 + j] = ((w1 >> j) & 1u) ? __uint_as_float(sr[j]) * ATT_SCALE : -1e9f;

        // online softmax
        float mloc = -1e30f;
        #pragma unroll
        for (int j = 0; j < 64; j++) mloc = fmaxf(mloc, s[j]);
        (hf ? redB : redA)[qrow] = mloc;
        __syncthreads();
        float mx = fmaxf(redA[qrow], redB[qrow]);
        float mnew = fmaxf(mrow, mx);
        float alpha = __expf(mrow - mnew);
        mrow = mnew;
        __syncthreads();
        float ps = 0.f;
        #pragma unroll
        for (int j = 0; j < 64; j++) {
            float p = __expf(s[j] - mnew);
            s[j] = p;
            ps += p;
        }
        (hf ? redB : redA)[qrow] = ps;
        __syncthreads();
        lrow = lrow * alpha + redA[qrow] + redB[qrow];

        // P -> bf16 hi/lo into TMEM
        uint32_t pv[32];
        #pragma unroll
        for (int c = 0; c < 32; c++) pv[c] = pack2(f2bf(s[2 * c]), f2bf(s[2 * c + 1]));
        TC_ST_X32(tmem + hf * 32 + woff, pv);
        #pragma unroll
        for (int c = 0; c < 32; c++) pv[c] = pack2(f2bf_lo(s[2 * c]), f2bf_lo(s[2 * c + 1]));
        TC_ST_X32(tmem + 64 + hf * 32 + woff, pv);
        TC_WAIT_ST();
        TC_FENCE_BEFORE();
        __syncthreads();

        // MMA2: Dtmp = P V (3-term, TS)
        if (wid == 0 && elect_one_pred()) {
            TC_FENCE_AFTER();
            uint64_t vhiA = make_desc(sb + AT_VHI_A);
            uint64_t vhiB = make_desc(sb + AT_VHI_B);
            uint64_t vloA = make_desc(sb + AT_VLO_A);
            uint64_t vloB = make_desc(sb + AT_VLO_B);
            bool first = true;
            #pragma unroll
            for (int s8 = 0; s8 < 8; s8++) {
                uint64_t bd = (s8 < 4 ? vhiA + 2 * s8 : vhiB + 2 * (s8 - 4));
                mma_f16_ts(tmem + 128, tmem + 0 + s8 * 8, bd, IDESC_N64, !first);
                first = false;
            }
            #pragma unroll
            for (int s8 = 0; s8 < 8; s8++) {
                uint64_t bd = (s8 < 4 ? vhiA + 2 * s8 : vhiB + 2 * (s8 - 4));
                mma_f16_ts(tmem + 128, tmem + 64 + s8 * 8, bd, IDESC_N64, true);
            }
            #pragma unroll
            for (int s8 = 0; s8 < 8; s8++) {
                uint64_t bd = (s8 < 4 ? vloA + 2 * s8 : vloB + 2 * (s8 - 4));
                mma_f16_ts(tmem + 128, tmem + 0 + s8 * 8, bd, IDESC_N64, true);
            }
            TC_COMMIT(sb + 24);
        }
        MBAR_WAIT(sb + 24, ph2); ph2 ^= 1;
        TC_FENCE_AFTER();

        uint32_t dr[32];
        TC_LD_X32(dr, tmem + 128 + hf * 32);
        TC_WAIT_LD();
        TC_FENCE_BEFORE();
        #pragma unroll
        for (int j = 0; j < 32; j++)
            acc[j] = acc[j] * alpha + __uint_as_float(dr[j]);
    }

    // output -> ctx images
    {
        float invl = 1.0f / lrow;
        unsigned char* chi = ctxImg + img_off(b * 4 + qt, h, 0);
        unsigned char* clo = ctxImg + img_off(b * 4 + qt, h, 1);
        #pragma unroll
        for (int j = 0; j < 32; j += 2) {
            float v0 = acc[j] * invl, v1 = acc[j + 1] * invl;
            uint32_t off = qrow * 128 + (hf * 32 + j) * 2;
            off ^= (off >> 3) & 0x70;
            *(uint32_t*)(chi + off) = pack2(f2bf(v0), f2bf(v1));
            *(uint32_t*)(clo + off) = pack2(f2bf_lo(v0), f2bf_lo(v1));
        }
    }

    __syncthreads();
    if (tid == 0) { MBAR_INVAL(sb + 16); MBAR_INVAL(sb + 24); }
    __syncthreads();
    if (wid == 0) TC_DEALLOC(tmem, 256);
#endif
}

// res = LN_eff( LN_outer(h + ffn) ); scatter-add into upd and out.
__global__ __launch_bounds__(256)
void final_scatter_kernel(const float* __restrict__ hbuf, const float* __restrict__ fbuf,
                          const int* __restrict__ idx,
                          const float* __restrict__ os, const float* __restrict__ ob,
                          const float* __restrict__ es, const float* __restrict__ eb,
                          float* __restrict__ upd, float* __restrict__ out) {
    __shared__ float red[16];
    int r = blockIdx.x, b = blockIdx.y, t = threadIdx.x;
    size_t row = ((size_t)b * NQ + r) * Dm;
    float x = hbuf[row + t] + fbuf[row + t];
    float2 mv = block_meanrstd(x, red);
    float y = (x - mv.x) * mv.y * os[t] + ob[t];
    float2 mv2 = block_meanrstd(y, red);
    float res = (y - mv2.x) * mv2.y * es[t] + eb[t];
    int j = idx[r];
    size_t o = ((size_t)b * NS + j) * Dm + t;
    atomicAdd(&upd[o], res);
    atomicAdd(&out[o], res);
}

// ---------------- host launcher ----------------
extern "C" void kernel_launch(void* const* d_in, const int* in_sizes, int n_in,
                              void* d_out, int out_size) {
    const float* update = (const float*)d_in[0];
    const float* emb    = (const float*)d_in[1];
    const float* mask   = (const float*)d_in[2];
    const float* Wq     = (const float*)d_in[3];
    const float* Wk     = (const float*)d_in[4];
    const float* Wv     = (const float*)d_in[5];
    const float* Wo     = (const float*)d_in[6];
    const float* W1     = (const float*)d_in[7];
    const float* b1     = (const float*)d_in[8];
    const float* W2     = (const float*)d_in[9];
    const float* b2     = (const float*)d_in[10];
    const float* sys_s  = (const float*)d_in[11];
    const float* sys_b  = (const float*)d_in[12];
    const float* eff_s  = (const float*)d_in[13];
    const float* eff_b  = (const float*)d_in[14];
    const float* in_s   = (const float*)d_in[15];
    const float* in_b   = (const float*)d_in[16];
    const float* out_s  = (const float*)d_in[17];
    const float* out_b  = (const float*)d_in[18];
    const int*   qidx   = (const int*)d_in[19];
    const int*   kidx   = (const int*)d_in[20];
    float* out = (float*)d_out;

    float *p_upd, *p_h, *p_wo, *p_r;
    uint32_t* p_mb;
    __nv_bfloat16* p_w;
    unsigned char *p_iqn, *p_ikn, *p_iQ, *p_iK, *p_iVt, *p_ictx, *p_ih, *p_it;
    cudaGetSymbolAddress((void**)&p_upd, g_upd);
    cudaGetSymbolAddress((void**)&p_h,   g_h);
    cudaGetSymbolAddress((void**)&p_wo,  g_wo);
    cudaGetSymbolAddress((void**)&p_r,   g_r);
    cudaGetSymbolAddress((void**)&p_mb,  g_mbits);
    cudaGetSymbolAddress((void**)&p_w,   g_wprep);
    cudaGetSymbolAddress((void**)&p_iqn, g_img_qn);
    cudaGetSymbolAddress((void**)&p_ikn, g_img_kn);
    cudaGetSymbolAddress((void**)&p_iQ,  g_img_Q);
    cudaGetSymbolAddress((void**)&p_iK,  g_img_K);
    cudaGetSymbolAddress((void**)&p_iVt, g_img_Vt);
    cudaGetSymbolAddress((void**)&p_ictx, g_img_ctx);
    cudaGetSymbolAddress((void**)&p_ih,  g_img_h);
    cudaGetSymbolAddress((void**)&p_it,  g_img_t);

    cudaFuncSetAttribute(gemm_img_kernel<0, 0>, cudaFuncAttributeMaxDynamicSharedMemorySize, GT_SMEM_TOTAL);
    cudaFuncSetAttribute(gemm_img_kernel<0, 1>, cudaFuncAttributeMaxDynamicSharedMemorySize, GT_SMEM_TOTAL);
    cudaFuncSetAttribute(gemm_img_kernel<0, 2>, cudaFuncAttributeMaxDynamicSharedMemorySize, GT_SMEM_TOTAL);
    cudaFuncSetAttribute(gemm_img_kernel<1, 0>, cudaFuncAttributeMaxDynamicSharedMemorySize, GT_SMEM_TOTAL);
    cudaFuncSetAttribute(gemm_img_kernel<2, 1>, cudaFuncAttributeMaxDynamicSharedMemorySize, GT_SMEM_TOTAL);
    cudaFuncSetAttribute(attn_tc_kernel, cudaFuncAttributeMaxDynamicSharedMemorySize, AT_SMEM_TOTAL);

    const size_t WCH = (size_t)12 * 256 * 64;

    cudaMemsetAsync(d_out, 0, (size_t)out_size * sizeof(float), 0);
    cudaMemcpyAsync(p_upd, update, (size_t)Bz * NS * Dm * sizeof(float),
                    cudaMemcpyDeviceToDevice, 0);

    prep_all_kernel<<<72 + Ll * 64, 256>>>(Wq, Wk, Wv, Wo, W1, W2, p_w, mask, p_mb);

    for (int l = 0; l < Ll; l++) {
        const int* qi = qidx + l * NQ;
        const int* ki = kidx + l * NK;
        const uint32_t* mb = p_mb + (size_t)l * NQ * (NK / 32);

        gather_ln_img_kernel<<<dim3(NQ, Bz), 256>>>(emb, p_upd, qi, sys_s, sys_b, p_iqn, NQ);
        gather_ln_img_kernel<<<dim3(NK, Bz), 256>>>(emb, p_upd, ki, sys_s, sys_b, p_ikn, NK);

        gemm_img_kernel<0, 1><<<(Bz * NQ) / 128, 256, GT_SMEM_TOTAL>>>(p_iqn, p_w + 0 * WCH, nullptr, nullptr, p_iQ);
        gemm_img_kernel<0, 1><<<(Bz * NK) / 128, 256, GT_SMEM_TOTAL>>>(p_ikn, p_w + 1 * WCH, nullptr, nullptr, p_iK);
        gemm_img_kernel<0, 2><<<(Bz * NK) / 128, 256, GT_SMEM_TOTAL>>>(p_ikn, p_w + 2 * WCH, nullptr, nullptr, p_iVt);

        attn_tc_kernel<<<dim3(NQ / 128, Hh, Bz), 256, AT_SMEM_TOTAL>>>(p_iQ, p_iK, p_iVt, mb, p_ictx);

        gemm_img_kernel<0, 0><<<(Bz * NQ) / 128, 256, GT_SMEM_TOTAL>>>(p_ictx, p_w + 3 * WCH, nullptr, p_wo, nullptr);
        row_ln_img_kernel<<<Bz * NQ, 256>>>(p_wo, in_s, in_b, p_h, p_ih);

        gemm_img_kernel<2, 1><<<(Bz * NQ) / 128, 256, GT_SMEM_TOTAL>>>(p_ih, p_w + 4 * WCH, b1, nullptr, p_it);
        gemm_img_kernel<1, 0><<<(Bz * NQ) / 128, 256, GT_SMEM_TOTAL>>>(p_it, p_w + 5 * WCH, b2, p_r, nullptr);

        final_scatter_kernel<<<dim3(NQ, Bz), 256>>>(p_h, p_r, qi,
                                                    out_s, out_b, eff_s, eff_b,
                                                    p_upd, out);
    }
}

// round 9
// speedup vs baseline: 3.6001x; 1.2628x over previous
#include <cuda_runtime.h>
#include <cuda_bf16.h>
#include <math.h>
#include <stdint.h>

#define Bz 32
#define NS 4096
#define Dm 256
#define Hh 4
#define DH 64
#define Ll 6
#define NQ 512
#define NK 1024
#define ATT_SCALE 0.125f

// ---------------- scratch (device globals; no allocation allowed) ----------------
__device__ float g_upd[(size_t)Bz * NS * Dm];
__device__ float g_h  [(size_t)Bz * NQ * Dm];
__device__ float g_wo [(size_t)Bz * NQ * Dm];
__device__ float g_r  [(size_t)Bz * NQ * Dm];
__device__ uint32_t g_mbits[(size_t)Ll * NQ * (NK / 32)];
// bf16 hi/lo swizzled tile images: [tile][g(4)][hilo(2)] x 16KB
__device__ unsigned char g_img_qn [(size_t)128 * 8 * 16384];
__device__ unsigned char g_img_kn [(size_t)256 * 8 * 16384];
__device__ unsigned char g_img_Q  [(size_t)128 * 8 * 16384];
__device__ unsigned char g_img_K  [(size_t)256 * 8 * 16384];
__device__ unsigned char g_img_ctx[(size_t)128 * 8 * 16384];
__device__ unsigned char g_img_h  [(size_t)128 * 8 * 16384];
__device__ unsigned char g_img_t  [(size_t)128 * 8 * 16384];
// V transposed images: [tile][h(4)][half(2)][hilo(2)] x 8KB
__device__ unsigned char g_img_Vt [(size_t)256 * 16 * 8192];
// prepped weights: 6 matrices x 12 chunks x 32KB (pre-swizzled B images)
__device__ __nv_bfloat16 g_wprep[(size_t)6 * 12 * 256 * 64];

__device__ __forceinline__ size_t img_off(int tile, int g, int hilo) {
    return (((size_t)tile * 4 + g) * 2 + hilo) << 14;
}
__device__ __forceinline__ size_t imgv_off(int tile, int h, int half, int hilo) {
    return ((((size_t)tile * 4 + h) * 2 + half) * 2 + hilo) << 13;
}

// ---------------- small helpers ----------------
__device__ __forceinline__ uint32_t smem_u32(const void* p) {
    uint32_t a;
    asm("{ .reg .u64 t; cvta.to.shared.u64 t, %1; cvt.u32.u64 %0, t; }" : "=r"(a) : "l"(p));
    return a;
}
__device__ __forceinline__ unsigned short f2bf(float x) {
    __nv_bfloat16 b = __float2bfloat16_rn(x);
    return *reinterpret_cast<unsigned short*>(&b);
}
__device__ __forceinline__ unsigned short f2bf_lo(float x) {
    __nv_bfloat16 b = __float2bfloat16_rn(x);
    float hi = __bfloat162float(b);
    __nv_bfloat16 l = __float2bfloat16_rn(x - hi);
    return *reinterpret_cast<unsigned short*>(&l);
}
__device__ __forceinline__ uint32_t pack2(unsigned short a, unsigned short b) {
    return (uint32_t)a | ((uint32_t)b << 16);
}

__device__ __forceinline__ float2 block_meanrstd(float x, float* red) {
    float s1 = x, s2 = x * x;
    #pragma unroll
    for (int o = 16; o > 0; o >>= 1) {
        s1 += __shfl_xor_sync(0xffffffffu, s1, o);
        s2 += __shfl_xor_sync(0xffffffffu, s2, o);
    }
    int w = threadIdx.x >> 5, ln = threadIdx.x & 31;
    if (ln == 0) { red[w] = s1; red[8 + w] = s2; }
    __syncthreads();
    float m = 0.f, q = 0.f;
    #pragma unroll
    for (int i = 0; i < 8; i++) { m += red[i]; q += red[8 + i]; }
    __syncthreads();
    m *= (1.0f / Dm);
    q = q * (1.0f / Dm) - m * m;
    return make_float2(m, rsqrtf(fmaxf(q, 0.f) + 1e-5f));
}

__device__ __forceinline__ float gelu_tanh(float x) {
    const float c = 0.7978845608028654f;
    float t = tanhf(c * (x + 0.044715f * x * x * x));
    return 0.5f * x * (1.0f + t);
}

// ---------------- mbarrier / bulk-copy plumbing ----------------
#define MBAR_INIT(addr, cnt) \
    asm volatile("mbarrier.init.shared.b64 [%0], %1;" :: "r"(addr), "r"(cnt) : "memory")
#define MBAR_INVAL(addr) \
    asm volatile("mbarrier.inval.shared.b64 [%0];" :: "r"(addr) : "memory")
#define MBAR_EXPECT(addr, bytes) \
    asm volatile("mbarrier.arrive.expect_tx.shared.b64 _, [%0], %1;" :: "r"(addr), "r"(bytes) : "memory")
#define MBAR_WAIT(addr, par) do { \
    uint32_t _m = (addr); uint32_t _p = (par); uint32_t _d; \
    asm volatile("{\n\t.reg .pred p;\n\t" \
        "mbarrier.try_wait.parity.acquire.cta.shared::cta.b64 p, [%1], %2;\n\t" \
        "selp.b32 %0, 1, 0, p;\n\t}" : "=r"(_d) : "r"(_m), "r"(_p) : "memory"); \
    if (!_d) { \
        asm volatile("{\n\t.reg .pred P1;\n\t" \
            "W_%=:\n\t" \
            "mbarrier.try_wait.parity.acquire.cta.shared::cta.b64 P1, [%0], %1, 0x989680;\n\t" \
            "@P1 bra.uni D_%=;\n\t" \
            "bra.uni W_%=;\n\t" \
            "D_%=:\n\t}" :: "r"(_m), "r"(_p) : "memory"); \
    } } while (0)

__device__ __forceinline__ void bulk_cp(uint32_t dst, const void* src, uint32_t bytes,
                                        uint32_t mbar) {
    asm volatile(
        "cp.async.bulk.shared::cta.global.mbarrier::complete_tx::bytes [%0], [%1], %2, [%3];"
        :: "r"(dst), "l"(src), "r"(bytes), "r"(mbar) : "memory");
}

#if defined(__CUDA_ARCH_FEAT_SM103_ALL)
#define TC_ALLOC(sa, n) \
    asm volatile("tcgen05.alloc.cta_group::1.sync.aligned.shared::cta.b32 [%0], %1;" \
        :: "r"(sa), "r"(n) : "memory")
#define TC_RELINQ() \
    asm volatile("tcgen05.relinquish_alloc_permit.cta_group::1.sync.aligned;")
#define TC_DEALLOC(t, n) \
    asm volatile("tcgen05.dealloc.cta_group::1.sync.aligned.b32 %0, %1;" :: "r"(t), "r"(n))
#define TC_COMMIT(mb) \
    asm volatile("tcgen05.commit.cta_group::1.mbarrier::arrive::one.shared::cluster.b64 [%0];" \
        :: "r"(mb) : "memory")
#define TC_FENCE_AFTER() asm volatile("tcgen05.fence::after_thread_sync;" ::: "memory")
#define TC_FENCE_BEFORE() asm volatile("tcgen05.fence::before_thread_sync;" ::: "memory")
#define TC_WAIT_LD() asm volatile("tcgen05.wait::ld.sync.aligned;" ::: "memory")
#define TC_WAIT_ST() asm volatile("tcgen05.wait::st.sync.aligned;" ::: "memory")

#define TC_LD_X32(r, ta) \
    asm volatile("tcgen05.ld.sync.aligned.32x32b.x32.b32 " \
        "{%0, %1, %2, %3, %4, %5, %6, %7, %8, %9, %10, %11, %12, %13, %14, %15, " \
        "%16, %17, %18, %19, %20, %21, %22, %23, %24, %25, %26, %27, %28, %29, %30, %31}, [%32];" \
        : "=r"((r)[0]), "=r"((r)[1]), "=r"((r)[2]), "=r"((r)[3]), \
          "=r"((r)[4]), "=r"((r)[5]), "=r"((r)[6]), "=r"((r)[7]), \
          "=r"((r)[8]), "=r"((r)[9]), "=r"((r)[10]), "=r"((r)[11]), \
          "=r"((r)[12]), "=r"((r)[13]), "=r"((r)[14]), "=r"((r)[15]), \
          "=r"((r)[16]), "=r"((r)[17]), "=r"((r)[18]), "=r"((r)[19]), \
          "=r"((r)[20]), "=r"((r)[21]), "=r"((r)[22]), "=r"((r)[23]), \
          "=r"((r)[24]), "=r"((r)[25]), "=r"((r)[26]), "=r"((r)[27]), \
          "=r"((r)[28]), "=r"((r)[29]), "=r"((r)[30]), "=r"((r)[31]) \
        : "r"(ta))

#define TC_ST_X32(ta, r) \
    asm volatile("tcgen05.st.sync.aligned.32x32b.x32.b32 [%0], " \
        "{%1, %2, %3, %4, %5, %6, %7, %8, %9, %10, %11, %12, %13, %14, %15, %16, " \
        "%17, %18, %19, %20, %21, %22, %23, %24, %25, %26, %27, %28, %29, %30, %31, %32};" \
        :: "r"(ta), \
           "r"((r)[0]), "r"((r)[1]), "r"((r)[2]), "r"((r)[3]), \
           "r"((r)[4]), "r"((r)[5]), "r"((r)[6]), "r"((r)[7]), \
           "r"((r)[8]), "r"((r)[9]), "r"((r)[10]), "r"((r)[11]), \
           "r"((r)[12]), "r"((r)[13]), "r"((r)[14]), "r"((r)[15]), \
           "r"((r)[16]), "r"((r)[17]), "r"((r)[18]), "r"((r)[19]), \
           "r"((r)[20]), "r"((r)[21]), "r"((r)[22]), "r"((r)[23]), \
           "r"((r)[24]), "r"((r)[25]), "r"((r)[26]), "r"((r)[27]), \
           "r"((r)[28]), "r"((r)[29]), "r"((r)[30]), "r"((r)[31]) \
        : "memory")

__device__ __forceinline__ void mma_f16_ss(uint32_t d, uint64_t ad, uint64_t bd,
                                           uint32_t idesc, bool acc) {
    uint32_t en = acc ? 1u : 0u;
    asm volatile(
        "{\n\t.reg .pred p;\n\t"
        "setp.ne.u32 p, %5, 0;\n\t"
        "tcgen05.mma.cta_group::1.kind::f16 [%0], %1, %2, %3, {%4, %4, %4, %4}, p;\n\t"
        "}"
        :: "r"(d), "l"(ad), "l"(bd), "r"(idesc), "r"(0u), "r"(en)
        : "memory");
}
__device__ __forceinline__ void mma_f16_ts(uint32_t d, uint32_t a, uint64_t bd,
                                           uint32_t idesc, bool acc) {
    uint32_t en = acc ? 1u : 0u;
    asm volatile(
        "{\n\t.reg .pred p;\n\t"
        "setp.ne.u32 p, %5, 0;\n\t"
        "tcgen05.mma.cta_group::1.kind::f16 [%0], [%1], %2, %3, {%4, %4, %4, %4}, p;\n\t"
        "}"
        :: "r"(d), "r"(a), "l"(bd), "r"(idesc), "r"(0u), "r"(en)
        : "memory");
}
#endif

static constexpr uint64_t DESC_BASE_SW128 =
    (2ull << 61) | (1ull << 46) | (64ull << 32) | (1ull << 16);
__device__ __forceinline__ uint64_t make_desc(uint32_t addr) {
    return DESC_BASE_SW128 | ((uint64_t)(addr >> 4) & 0x3FFF);
}

#define IDESC_N256 ((1u << 4) | (1u << 7) | (1u << 10) | ((256u / 8) << 17) | ((128u / 16) << 24))
#define IDESC_N128 ((1u << 4) | (1u << 7) | (1u << 10) | ((128u / 8) << 17) | ((128u / 16) << 24))
#define IDESC_N64  ((1u << 4) | (1u << 7) | (1u << 10) | ((64u  / 8) << 17) | ((128u / 16) << 24))

// GEMM SMEM: [0..15] tmem ptr, mbars full0-2 @16/24/32, done0-2 @40/48/56, final @64
// stages @1024 + s*49152 (A 16KB + B 32KB)
#define GT_SMEM_TOTAL (1024 + 3 * 49152)
// attention SMEM
#define AT_QHI   2048
#define AT_QLO   18432
#define AT_KHI   34816
#define AT_KLO   51200
#define AT_VHI_A 67584
#define AT_VHI_B 75776
#define AT_VLO_A 83968
#define AT_VLO_B 92160
#define AT_SMEM_TOTAL 100352

// ---------------- prep: weights + mask bits ----------------
__global__ __launch_bounds__(256)
void prep_all_kernel(const float* __restrict__ Wq, const float* __restrict__ Wk,
                     const float* __restrict__ Wv, const float* __restrict__ Wo,
                     const float* __restrict__ W1, const float* __restrict__ W2,
                     __nv_bfloat16* __restrict__ wprep,
                     const float* __restrict__ mask, uint32_t* __restrict__ bits) {
    int bx = blockIdx.x;
    if (bx < 72) {
        int w = bx / 12, c = bx % 12;
        const float* W = (w == 0) ? Wq : (w == 1) ? Wk : (w == 2) ? Wv
                       : (w == 3) ? Wo : (w == 4) ? W1 : W2;
        int g = c / 3, t = c % 3, n = threadIdx.x;
        char* base = (char*)wprep + ((size_t)w * 12 + c) * 32768;
        #pragma unroll 4
        for (int j = 0; j < 64; j += 2) {
            float x0 = W[(size_t)(64 * g + j) * 256 + n];
            float x1 = W[(size_t)(64 * g + j + 1) * 256 + n];
            unsigned short h0 = (t == 2) ? f2bf_lo(x0) : f2bf(x0);
            unsigned short h1 = (t == 2) ? f2bf_lo(x1) : f2bf(x1);
            uint32_t off = n * 128 + j * 2;
            off ^= (off >> 3) & 0x70;
            *(uint32_t*)(base + off) = pack2(h0, h1);
        }
    } else {
        int idx = bx - 72;
        int lev = idx >> 6, rblk = idx & 63;
        int w = threadIdx.x >> 5, l = threadIdx.x & 31;
        int r = rblk * 8 + w;
        const float* row = mask + ((size_t)lev * NQ + r) * NK;
        uint32_t myword = 0;
        for (int j = 0; j < 32; j++) {
            uint32_t bal = __ballot_sync(0xffffffffu, row[j * 32 + l] > 0.5f);
            if (l == j) myword = bal;
        }
        bits[((size_t)lev * NQ + r) * 32 + l] = myword;
    }
}

// ---------------- gather + LN -> images (q and k merged) ----------------
__global__ __launch_bounds__(256)
void gather_ln_img_kernel(const float* __restrict__ emb, const float* __restrict__ upd,
                          const int* __restrict__ qi, const int* __restrict__ ki,
                          const float* __restrict__ sc, const float* __restrict__ bi,
                          unsigned char* __restrict__ imgq, unsigned char* __restrict__ imgk) {
    __shared__ float red[16];
    int r = blockIdx.x, b = blockIdx.y, t = threadIdx.x;
    const int* idx;
    unsigned char* img;
    int rr, nrows;
    if (r < NQ) { idx = qi; img = imgq; rr = r; nrows = NQ; }
    else        { idx = ki; img = imgk; rr = r - NQ; nrows = NK; }
    int j = idx[rr];
    float x = emb[(size_t)j * Dm + t] + upd[((size_t)b * NS + j) * Dm + t];
    float2 mv = block_meanrstd(x, red);
    float y = (x - mv.x) * mv.y * sc[t] + bi[t];
    int row = b * nrows + rr;
    int tile = row >> 7, r7 = row & 127;
    int g = t >> 6, c = t & 63;
    uint32_t off = r7 * 128 + c * 2;
    off ^= (off >> 3) & 0x70;
    *(unsigned short*)(img + img_off(tile, g, 0) + off) = f2bf(y);
    *(unsigned short*)(img + img_off(tile, g, 1) + off) = f2bf_lo(y);
}

// row LN -> fp32 + images
__global__ __launch_bounds__(256)
void row_ln_img_kernel(const float* __restrict__ in,
                       const float* __restrict__ sc, const float* __restrict__ bi,
                       float* __restrict__ outf, unsigned char* __restrict__ img) {
    __shared__ float red[16];
    int row = blockIdx.x, t = threadIdx.x;
    float x = in[(size_t)row * Dm + t];
    float2 mv = block_meanrstd(x, red);
    float y = (x - mv.x) * mv.y * sc[t] + bi[t];
    outf[(size_t)row * Dm + t] = y;
    int tile = row >> 7, rr = row & 127;
    int g = t >> 6, c = t & 63;
    uint32_t off = rr * 128 + c * 2;
    off ^= (off >> 3) & 0x70;
    *(unsigned short*)(img + img_off(tile, g, 0) + off) = f2bf(y);
    *(unsigned short*)(img + img_off(tile, g, 1) + off) = f2bf_lo(y);
}

// ---------------- tc GEMM pipeline body (bulk-copy 3-stage) ----------------
__device__ __forceinline__ void gemm_body(const unsigned char* __restrict__ Aimg,
                                          const __nv_bfloat16* __restrict__ Wp,
                                          const float* __restrict__ bias,
                                          float* __restrict__ Cf,
                                          unsigned char* __restrict__ Cimg,
                                          int tile, int epi, int outmode) {
#if defined(__CUDA_ARCH_FEAT_SM103_ALL)
    extern __shared__ char smem[];
    uint32_t sb = smem_u32(smem);
    int tid = threadIdx.x, wid = tid >> 5, lane = tid & 31;

    if (wid == 0) { TC_ALLOC(sb + 0, 256); TC_RELINQ(); }
    if (tid == 0) {
        #pragma unroll
        for (int i = 0; i < 7; i++) MBAR_INIT(sb + 16 + 8 * i, 1);
    }
    __syncthreads();
    uint32_t tmem;
    asm volatile("ld.shared.b32 %0, [%1];" : "=r"(tmem) : "r"(sb + 0));

    if (tid == 0) {
        auto issue_chunk = [&](int c, int s) {
            int g = c / 3, tt = c % 3;
            int aidx = tile * 8 + g * 2 + (tt == 1 ? 1 : 0);
            uint32_t fm = sb + 16 + 8 * s;
            uint32_t sa = sb + 1024 + s * 49152;
            MBAR_EXPECT(fm, 49152);
            bulk_cp(sa, Aimg + ((size_t)aidx << 14), 16384, fm);
            bulk_cp(sa + 16384, (const unsigned char*)Wp + ((size_t)c << 15), 32768, fm);
        };
        issue_chunk(0, 0); issue_chunk(1, 1); issue_chunk(2, 2);
        int fph0 = 0, fph1 = 0, fph2 = 0, dph0 = 0, dph1 = 0, dph2 = 0;
        for (int c = 0; c < 12; c++) {
            int s = c % 3;
            int fp = (s == 0) ? fph0 : (s == 1) ? fph1 : fph2;
            MBAR_WAIT(sb + 16 + 8 * s, fp);
            if (s == 0) fph0 ^= 1; else if (s == 1) fph1 ^= 1; else fph2 ^= 1;
            uint32_t sa = sb + 1024 + s * 49152;
            uint64_t ad = make_desc(sa);
            uint64_t bd = make_desc(sa + 16384);
            #pragma unroll
            for (int k = 0; k < 4; k++)
                mma_f16_ss(tmem, ad + 2 * k, bd + 2 * k, IDESC_N256, (c > 0) || (k > 0));
            if (c <= 8) {
                TC_COMMIT(sb + 40 + 8 * s);
                int dp = (s == 0) ? dph0 : (s == 1) ? dph1 : dph2;
                MBAR_WAIT(sb + 40 + 8 * s, dp);
                if (s == 0) dph0 ^= 1; else if (s == 1) dph1 ^= 1; else dph2 ^= 1;
                issue_chunk(c + 3, s);
            } else if (c == 11) {
                TC_COMMIT(sb + 64);
            }
        }
    }
    MBAR_WAIT(sb + 64, 0);
    TC_FENCE_AFTER();
    __syncthreads();

    if (outmode == 0) {
        float* stage = (float*)(smem + 1024);
        for (int p = 0; p < 8; p++) {
            if (wid < 4) {
                uint32_t regs[32];
                TC_LD_X32(regs, tmem + p * 32);
                TC_WAIT_LD();
                int row = wid * 32 + lane;
                #pragma unroll
                for (int j = 0; j < 32; j++) {
                    float v = __uint_as_float(regs[j]);
                    if (epi >= 1) v += bias[p * 32 + j];
                    if (epi == 2) v = gelu_tanh(v);
                    stage[row * 33 + j] = v;
                }
            }
            __syncthreads();
            #pragma unroll
            for (int i = 0; i < 16; i++) {
                int row = wid + 8 * i;
                Cf[((size_t)tile * 128 + row) * 256 + p * 32 + lane] = stage[row * 33 + lane];
            }
            __syncthreads();
        }
    } else {
        int sp = wid & 3, hf = wid >> 2;
        int rr = sp * 32 + lane;
        for (int p = hf * 4; p < hf * 4 + 4; p++) {
            uint32_t regs[32];
            TC_LD_X32(regs, tmem + p * 32);
            TC_WAIT_LD();
            float v[32];
            #pragma unroll
            for (int j = 0; j < 32; j++) {
                float u = __uint_as_float(regs[j]);
                if (epi >= 1) u += bias[p * 32 + j];
                if (epi == 2) u = gelu_tanh(u);
                v[j] = u;
            }
            if (outmode == 1) {
                unsigned char* hi = Cimg + img_off(tile, p >> 1, 0);
                unsigned char* lo = Cimg + img_off(tile, p >> 1, 1);
                int cb = (p & 1) * 32;
                #pragma unroll
                for (int j = 0; j < 32; j += 2) {
                    uint32_t off = rr * 128 + (cb + j) * 2;
                    off ^= (off >> 3) & 0x70;
                    *(uint32_t*)(hi + off) = pack2(f2bf(v[j]), f2bf(v[j + 1]));
                    *(uint32_t*)(lo + off) = pack2(f2bf_lo(v[j]), f2bf_lo(v[j + 1]));
                }
            } else {
                int kv = rr & 63, half = rr >> 6;
                unsigned char* hi = Cimg + imgv_off(tile, p >> 1, half, 0);
                unsigned char* lo = Cimg + imgv_off(tile, p >> 1, half, 1);
                #pragma unroll
                for (int j = 0; j < 32; j++) {
                    int dd = (p & 1) * 32 + j;
                    uint32_t off = dd * 128 + kv * 2;
                    off ^= (off >> 3) & 0x70;
                    *(unsigned short*)(hi + off) = f2bf(v[j]);
                    *(unsigned short*)(lo + off) = f2bf_lo(v[j]);
                }
            }
        }
    }

    __syncthreads();
    if (tid == 0) {
        #pragma unroll
        for (int i = 0; i < 7; i++) MBAR_INVAL(sb + 16 + 8 * i);
    }
    __syncthreads();
    if (wid == 0) TC_DEALLOC(tmem, 256);
#endif
}

// single-operand GEMM launch
__global__ __launch_bounds__(256)
void gemm_tc_kernel(const unsigned char* __restrict__ Aimg,
                    const __nv_bfloat16* __restrict__ Wp,
                    const float* __restrict__ bias,
                    float* __restrict__ Cf, unsigned char* __restrict__ Cimg,
                    int epi, int outmode) {
    gemm_body(Aimg, Wp, bias, Cf, Cimg, blockIdx.x, epi, outmode);
}

// merged QKV: grid = 128 + 256 + 256
__global__ __launch_bounds__(256)
void qkv_tc_kernel(const unsigned char* __restrict__ qnImg,
                   const unsigned char* __restrict__ knImg,
                   const __nv_bfloat16* __restrict__ wprep,
                   unsigned char* __restrict__ imgQ,
                   unsigned char* __restrict__ imgK,
                   unsigned char* __restrict__ imgVt) {
    const size_t WCH = (size_t)12 * 256 * 64;
    int bx = blockIdx.x;
    if (bx < 128)
        gemm_body(qnImg, wprep + 0 * WCH, nullptr, nullptr, imgQ, bx, 0, 1);
    else if (bx < 384)
        gemm_body(knImg, wprep + 1 * WCH, nullptr, nullptr, imgK, bx - 128, 0, 1);
    else
        gemm_body(knImg, wprep + 2 * WCH, nullptr, nullptr, imgVt, bx - 384, 0, 2);
}

// ---------------- tc flash attention (bulk copies + prefetch) ----------------
// grid: (NQ/128, H, B), 256 threads.
__global__ __launch_bounds__(256, 2)
void attn_tc_kernel(const unsigned char* __restrict__ Qimg,
                    const unsigned char* __restrict__ Kimg,
                    const unsigned char* __restrict__ Vimg,
                    const uint32_t* __restrict__ mbits,
                    unsigned char* __restrict__ ctxImg) {
#if defined(__CUDA_ARCH_FEAT_SM103_ALL)
    extern __shared__ char smem[];
    uint32_t sb = smem_u32(smem);
    int qt = blockIdx.x, h = blockIdx.y, b = blockIdx.z;
    int tid = threadIdx.x, wid = tid >> 5, lane = tid & 31;
    int sp = wid & 3, hf = wid >> 2;
    float* redA = (float*)(smem + 64);
    float* redB = (float*)(smem + 64 + 512);

    if (wid == 0) { TC_ALLOC(sb + 0, 256); TC_RELINQ(); }
    if (tid == 0) {
        MBAR_INIT(sb + 16, 1);  // mma1
        MBAR_INIT(sb + 24, 1);  // mma2
        MBAR_INIT(sb + 32, 1);  // K full
        MBAR_INIT(sb + 40, 1);  // V full
        MBAR_INIT(sb + 48, 1);  // Q full
    }
    __syncthreads();
    uint32_t tmem;
    asm volatile("ld.shared.b32 %0, [%1];" : "=r"(tmem) : "r"(sb + 0));

    auto issueK = [&](int t) {
        int kt = b * 8 + t;
        MBAR_EXPECT(sb + 32, 32768);
        bulk_cp(sb + AT_KHI, Kimg + img_off(kt, h, 0), 16384, sb + 32);
        bulk_cp(sb + AT_KLO, Kimg + img_off(kt, h, 1), 16384, sb + 32);
    };
    auto issueV = [&](int t) {
        int kt = b * 8 + t;
        MBAR_EXPECT(sb + 40, 32768);
        bulk_cp(sb + AT_VHI_A, Vimg + imgv_off(kt, h, 0, 0), 8192, sb + 40);
        bulk_cp(sb + AT_VHI_B, Vimg + imgv_off(kt, h, 1, 0), 8192, sb + 40);
        bulk_cp(sb + AT_VLO_A, Vimg + imgv_off(kt, h, 0, 1), 8192, sb + 40);
        bulk_cp(sb + AT_VLO_B, Vimg + imgv_off(kt, h, 1, 1), 8192, sb + 40);
    };
    if (tid == 0) {
        MBAR_EXPECT(sb + 48, 32768);
        bulk_cp(sb + AT_QHI, Qimg + img_off(b * 4 + qt, h, 0), 16384, sb + 48);
        bulk_cp(sb + AT_QLO, Qimg + img_off(b * 4 + qt, h, 1), 16384, sb + 48);
        issueK(0);
        issueV(0);
    }

    int qrow = sp * 32 + lane;
    const uint32_t* rowbits = mbits + (size_t)(qt * 128 + qrow) * 32 + hf * 2;
    float mrow = -1e30f, lrow = 0.f;
    float acc[32];
    #pragma unroll
    for (int j = 0; j < 32; j++) acc[j] = 0.f;

    int ph1 = 0, ph2 = 0, kph = 0, vph = 0;

    for (int t = 0; t < 8; t++) {
        int k0 = t * 128;
        // MMA1: S = Q K^T (3-term)
        if (tid == 0) {
            if (t == 0) MBAR_WAIT(sb + 48, 0);
            MBAR_WAIT(sb + 32, kph);
            uint64_t qhiD = make_desc(sb + AT_QHI);
            uint64_t qloD = make_desc(sb + AT_QLO);
            uint64_t khiD = make_desc(sb + AT_KHI);
            uint64_t kloD = make_desc(sb + AT_KLO);
            bool first = true;
            #pragma unroll
            for (int k = 0; k < 4; k++) { mma_f16_ss(tmem, qhiD + 2 * k, khiD + 2 * k, IDESC_N128, !first); first = false; }
            #pragma unroll
            for (int k = 0; k < 4; k++) mma_f16_ss(tmem, qloD + 2 * k, khiD + 2 * k, IDESC_N128, true);
            #pragma unroll
            for (int k = 0; k < 4; k++) mma_f16_ss(tmem, qhiD + 2 * k, kloD + 2 * k, IDESC_N128, true);
            TC_COMMIT(sb + 16);
        }
        kph ^= 1;
        MBAR_WAIT(sb + 16, ph1); ph1 ^= 1;
        TC_FENCE_AFTER();
        // prefetch K for next tile (K smem free now)
        if (tid == 0 && t < 7) issueK(t + 1);

        // read S, mask + scale
        uint32_t sr[32];
        float s[64];
        TC_LD_X32(sr, tmem + hf * 64);
        TC_WAIT_LD();
        uint32_t w0 = rowbits[(k0 >> 5)];
        #pragma unroll
        for (int j = 0; j < 32; j++)
            s[j] = ((w0 >> j) & 1u) ? __uint_as_float(sr[j]) * ATT_SCALE : -1e9f;
        TC_LD_X32(sr, tmem + hf * 64 + 32);
        TC_WAIT_LD();
        uint32_t w1 = rowbits[(k0 >> 5) + 1];
        #pragma unroll
        for (int j = 0; j < 32; j++)
            s[32 + j] = ((w1 >> j) & 1u) ? __uint_as_float(sr[j]) * ATT_SCALE : -1e9f;

        // online softmax
        float mloc = -1e30f;
        #pragma unroll
        for (int j = 0; j < 64; j++) mloc = fmaxf(mloc, s[j]);
        (hf ? redB : redA)[qrow] = mloc;
        __syncthreads();
        float mx = fmaxf(redA[qrow], redB[qrow]);
        float mnew = fmaxf(mrow, mx);
        float alpha = __expf(mrow - mnew);
        mrow = mnew;
        __syncthreads();
        float ps = 0.f;
        #pragma unroll
        for (int j = 0; j < 64; j++) {
            float p = __expf(s[j] - mnew);
            s[j] = p;
            ps += p;
        }
        (hf ? redB : redA)[qrow] = ps;
        __syncthreads();
        lrow = lrow * alpha + redA[qrow] + redB[qrow];

        // P -> bf16 hi/lo into TMEM
        uint32_t woff = (uint32_t)sp << 21;
        uint32_t pv[32];
        #pragma unroll
        for (int c = 0; c < 32; c++) pv[c] = pack2(f2bf(s[2 * c]), f2bf(s[2 * c + 1]));
        TC_ST_X32(tmem + hf * 32 + woff, pv);
        #pragma unroll
        for (int c = 0; c < 32; c++) pv[c] = pack2(f2bf_lo(s[2 * c]), f2bf_lo(s[2 * c + 1]));
        TC_ST_X32(tmem + 64 + hf * 32 + woff, pv);
        TC_WAIT_ST();
        TC_FENCE_BEFORE();
        __syncthreads();

        // MMA2: Dtmp = P V (3-term, TS)
        if (tid == 0) {
            MBAR_WAIT(sb + 40, vph);
            TC_FENCE_AFTER();
            uint64_t vhiA = make_desc(sb + AT_VHI_A);
            uint64_t vhiB = make_desc(sb + AT_VHI_B);
            uint64_t vloA = make_desc(sb + AT_VLO_A);
            uint64_t vloB = make_desc(sb + AT_VLO_B);
            bool first = true;
            #pragma unroll
            for (int s8 = 0; s8 < 8; s8++) {
                uint64_t bd = (s8 < 4 ? vhiA + 2 * s8 : vhiB + 2 * (s8 - 4));
                mma_f16_ts(tmem + 128, tmem + 0 + s8 * 8, bd, IDESC_N64, !first);
                first = false;
            }
            #pragma unroll
            for (int s8 = 0; s8 < 8; s8++) {
                uint64_t bd = (s8 < 4 ? vhiA + 2 * s8 : vhiB + 2 * (s8 - 4));
                mma_f16_ts(tmem + 128, tmem + 64 + s8 * 8, bd, IDESC_N64, true);
            }
            #pragma unroll
            for (int s8 = 0; s8 < 8; s8++) {
                uint64_t bd = (s8 < 4 ? vloA + 2 * s8 : vloB + 2 * (s8 - 4));
                mma_f16_ts(tmem + 128, tmem + 0 + s8 * 8, bd, IDESC_N64, true);
            }
            TC_COMMIT(sb + 24);
        }
        vph ^= 1;
        MBAR_WAIT(sb + 24, ph2); ph2 ^= 1;
        TC_FENCE_AFTER();
        // prefetch V for next tile
        if (tid == 0 && t < 7) issueV(t + 1);

        uint32_t dr[32];
        TC_LD_X32(dr, tmem + 128 + hf * 32);
        TC_WAIT_LD();
        TC_FENCE_BEFORE();
        #pragma unroll
        for (int j = 0; j < 32; j++)
            acc[j] = acc[j] * alpha + __uint_as_float(dr[j]);
    }

    // output -> ctx images
    {
        float invl = 1.0f / lrow;
        unsigned char* chi = ctxImg + img_off(b * 4 + qt, h, 0);
        unsigned char* clo = ctxImg + img_off(b * 4 + qt, h, 1);
        #pragma unroll
        for (int j = 0; j < 32; j += 2) {
            float v0 = acc[j] * invl, v1 = acc[j + 1] * invl;
            uint32_t off = qrow * 128 + (hf * 32 + j) * 2;
            off ^= (off >> 3) & 0x70;
            *(uint32_t*)(chi + off) = pack2(f2bf(v0), f2bf(v1));
            *(uint32_t*)(clo + off) = pack2(f2bf_lo(v0), f2bf_lo(v1));
        }
    }

    __syncthreads();
    if (tid == 0) {
        MBAR_INVAL(sb + 16); MBAR_INVAL(sb + 24); MBAR_INVAL(sb + 32);
        MBAR_INVAL(sb + 40); MBAR_INVAL(sb + 48);
    }
    __syncthreads();
    if (wid == 0) TC_DEALLOC(tmem, 256);
#endif
}

// res = LN_eff( LN_outer(h + ffn) ); scatter-add into upd and out.
__global__ __launch_bounds__(256)
void final_scatter_kernel(const float* __restrict__ hbuf, const float* __restrict__ fbuf,
                          const int* __restrict__ idx,
                          const float* __restrict__ os, const float* __restrict__ ob,
                          const float* __restrict__ es, const float* __restrict__ eb,
                          float* __restrict__ upd, float* __restrict__ out) {
    __shared__ float red[16];
    int r = blockIdx.x, b = blockIdx.y, t = threadIdx.x;
    size_t row = ((size_t)b * NQ + r) * Dm;
    float x = hbuf[row + t] + fbuf[row + t];
    float2 mv = block_meanrstd(x, red);
    float y = (x - mv.x) * mv.y * os[t] + ob[t];
    float2 mv2 = block_meanrstd(y, red);
    float res = (y - mv2.x) * mv2.y * es[t] + eb[t];
    int j = idx[r];
    size_t o = ((size_t)b * NS + j) * Dm + t;
    atomicAdd(&upd[o], res);
    atomicAdd(&out[o], res);
}

// ---------------- host launcher ----------------
extern "C" void kernel_launch(void* const* d_in, const int* in_sizes, int n_in,
                              void* d_out, int out_size) {
    const float* update = (const float*)d_in[0];
    const float* emb    = (const float*)d_in[1];
    const float* mask   = (const float*)d_in[2];
    const float* Wq     = (const float*)d_in[3];
    const float* Wk     = (const float*)d_in[4];
    const float* Wv     = (const float*)d_in[5];
    const float* Wo     = (const float*)d_in[6];
    const float* W1     = (const float*)d_in[7];
    const float* b1     = (const float*)d_in[8];
    const float* W2     = (const float*)d_in[9];
    const float* b2     = (const float*)d_in[10];
    const float* sys_s  = (const float*)d_in[11];
    const float* sys_b  = (const float*)d_in[12];
    const float* eff_s  = (const float*)d_in[13];
    const float* eff_b  = (const float*)d_in[14];
    const float* in_s   = (const float*)d_in[15];
    const float* in_b   = (const float*)d_in[16];
    const float* out_s  = (const float*)d_in[17];
    const float* out_b  = (const float*)d_in[18];
    const int*   qidx   = (const int*)d_in[19];
    const int*   kidx   = (const int*)d_in[20];
    float* out = (float*)d_out;

    float *p_upd, *p_h, *p_wo, *p_r;
    uint32_t* p_mb;
    __nv_bfloat16* p_w;
    unsigned char *p_iqn, *p_ikn, *p_iQ, *p_iK, *p_iVt, *p_ictx, *p_ih, *p_it;
    cudaGetSymbolAddress((void**)&p_upd, g_upd);
    cudaGetSymbolAddress((void**)&p_h,   g_h);
    cudaGetSymbolAddress((void**)&p_wo,  g_wo);
    cudaGetSymbolAddress((void**)&p_r,   g_r);
    cudaGetSymbolAddress((void**)&p_mb,  g_mbits);
    cudaGetSymbolAddress((void**)&p_w,   g_wprep);
    cudaGetSymbolAddress((void**)&p_iqn, g_img_qn);
    cudaGetSymbolAddress((void**)&p_ikn, g_img_kn);
    cudaGetSymbolAddress((void**)&p_iQ,  g_img_Q);
    cudaGetSymbolAddress((void**)&p_iK,  g_img_K);
    cudaGetSymbolAddress((void**)&p_iVt, g_img_Vt);
    cudaGetSymbolAddress((void**)&p_ictx, g_img_ctx);
    cudaGetSymbolAddress((void**)&p_ih,  g_img_h);
    cudaGetSymbolAddress((void**)&p_it,  g_img_t);

    cudaFuncSetAttribute(gemm_tc_kernel, cudaFuncAttributeMaxDynamicSharedMemorySize, GT_SMEM_TOTAL);
    cudaFuncSetAttribute(qkv_tc_kernel, cudaFuncAttributeMaxDynamicSharedMemorySize, GT_SMEM_TOTAL);
    cudaFuncSetAttribute(attn_tc_kernel, cudaFuncAttributeMaxDynamicSharedMemorySize, AT_SMEM_TOTAL);

    const size_t WCH = (size_t)12 * 256 * 64;

    cudaMemsetAsync(d_out, 0, (size_t)out_size * sizeof(float), 0);
    cudaMemcpyAsync(p_upd, update, (size_t)Bz * NS * Dm * sizeof(float),
                    cudaMemcpyDeviceToDevice, 0);

    prep_all_kernel<<<72 + Ll * 64, 256>>>(Wq, Wk, Wv, Wo, W1, W2, p_w, mask, p_mb);

    for (int l = 0; l < Ll; l++) {
        const int* qi = qidx + l * NQ;
        const int* ki = kidx + l * NK;
        const uint32_t* mb = p_mb + (size_t)l * NQ * (NK / 32);

        gather_ln_img_kernel<<<dim3(NQ + NK, Bz), 256>>>(emb, p_upd, qi, ki,
                                                         sys_s, sys_b, p_iqn, p_ikn);

        qkv_tc_kernel<<<640, 256, GT_SMEM_TOTAL>>>(p_iqn, p_ikn, p_w, p_iQ, p_iK, p_iVt);

        attn_tc_kernel<<<dim3(NQ / 128, Hh, Bz), 256, AT_SMEM_TOTAL>>>(p_iQ, p_iK, p_iVt, mb, p_ictx);

        gemm_tc_kernel<<<128, 256, GT_SMEM_TOTAL>>>(p_ictx, p_w + 3 * WCH, nullptr, p_wo, nullptr, 0, 0);
        row_ln_img_kernel<<<Bz * NQ, 256>>>(p_wo, in_s, in_b, p_h, p_ih);

        gemm_tc_kernel<<<128, 256, GT_SMEM_TOTAL>>>(p_ih, p_w + 4 * WCH, b1, nullptr, p_it, 2, 1);
        gemm_tc_kernel<<<128, 256, GT_SMEM_TOTAL>>>(p_it, p_w + 5 * WCH, b2, p_r, nullptr, 1, 0);

        final_scatter_kernel<<<dim3(NQ, Bz), 256>>>(p_h, p_r, qi,
                                                    out_s, out_b, eff_s, eff_b,
                                                    p_upd, out);
    }
}

// round 12
// speedup vs baseline: 4.2031x; 1.1675x over previous
#include <cuda_runtime.h>
#include <cuda_bf16.h>
#include <math.h>
#include <stdint.h>

#define Bz 32
#define NS 4096
#define Dm 256
#define Hh 4
#define DH 64
#define Ll 6
#define NQ 512
#define NK 1024
#define ATT_SCALE 0.125f

// ---------------- scratch ----------------
__device__ float g_upd[(size_t)Bz * NS * Dm];
__device__ float g_h  [(size_t)Bz * NQ * Dm];
__device__ uint32_t g_mbits[(size_t)Ll * NQ * (NK / 32)];
__device__ unsigned char g_img_qn [(size_t)128 * 8 * 16384];
__device__ unsigned char g_img_kn [(size_t)256 * 8 * 16384];
__device__ unsigned char g_img_Q  [(size_t)128 * 8 * 16384];
__device__ unsigned char g_img_K  [(size_t)256 * 8 * 16384];
__device__ unsigned char g_img_ctx[(size_t)128 * 8 * 16384];
__device__ unsigned char g_img_h  [(size_t)128 * 8 * 16384];
__device__ unsigned char g_img_t  [(size_t)128 * 8 * 16384];
__device__ unsigned char g_img_Vt [(size_t)256 * 16 * 8192];
__device__ __nv_bfloat16 g_wprep[(size_t)6 * 12 * 256 * 64];

__device__ __forceinline__ size_t img_off(int tile, int g, int hilo) {
    return (((size_t)tile * 4 + g) * 2 + hilo) << 14;
}
__device__ __forceinline__ size_t imgv_off(int tile, int h, int half, int hilo) {
    return ((((size_t)tile * 4 + h) * 2 + half) * 2 + hilo) << 13;
}

// ---------------- small helpers ----------------
__device__ __forceinline__ uint32_t smem_u32(const void* p) {
    uint32_t a;
    asm("{ .reg .u64 t; cvta.to.shared.u64 t, %1; cvt.u32.u64 %0, t; }" : "=r"(a) : "l"(p));
    return a;
}
__device__ __forceinline__ unsigned short f2bf(float x) {
    __nv_bfloat16 b = __float2bfloat16_rn(x);
    return *reinterpret_cast<unsigned short*>(&b);
}
__device__ __forceinline__ unsigned short f2bf_lo(float x) {
    __nv_bfloat16 b = __float2bfloat16_rn(x);
    float hi = __bfloat162float(b);
    __nv_bfloat16 l = __float2bfloat16_rn(x - hi);
    return *reinterpret_cast<unsigned short*>(&l);
}
__device__ __forceinline__ uint32_t pack2(unsigned short a, unsigned short b) {
    return (uint32_t)a | ((uint32_t)b << 16);
}
#define CVT2(res, a, b) asm("cvt.rn.bf16x2.f32 %0, %1, %2;" : "=r"(res) : "f"(b), "f"(a))

__device__ __forceinline__ void packhilo(float x0, float x1, uint32_t& hi, uint32_t& lo) {
    CVT2(hi, x0, x1);
    float h0 = __uint_as_float(hi << 16);
    float h1 = __uint_as_float(hi & 0xFFFF0000u);
    CVT2(lo, x0 - h0, x1 - h1);
}

__device__ __forceinline__ float gelu_tanh(float x) {
    const float c = 0.7978845608028654f;
    float t = tanhf(c * (x + 0.044715f * x * x * x));
    return 0.5f * x * (1.0f + t);
}

// ---------------- mbarrier / bulk-copy plumbing ----------------
#define MBAR_INIT(addr, cnt) \
    asm volatile("mbarrier.init.shared.b64 [%0], %1;" :: "r"(addr), "r"(cnt) : "memory")
#define MBAR_INVAL(addr) \
    asm volatile("mbarrier.inval.shared.b64 [%0];" :: "r"(addr) : "memory")
#define MBAR_EXPECT(addr, bytes) \
    asm volatile("mbarrier.arrive.expect_tx.shared.b64 _, [%0], %1;" :: "r"(addr), "r"(bytes) : "memory")
#define MBAR_WAIT(addr, par) do { \
    uint32_t _m = (addr); uint32_t _p = (par); uint32_t _d; \
    asm volatile("{\n\t.reg .pred p;\n\t" \
        "mbarrier.try_wait.parity.acquire.cta.shared::cta.b64 p, [%1], %2;\n\t" \
        "selp.b32 %0, 1, 0, p;\n\t}" : "=r"(_d) : "r"(_m), "r"(_p) : "memory"); \
    if (!_d) { \
        asm volatile("{\n\t.reg .pred P1;\n\t" \
            "W_%=:\n\t" \
            "mbarrier.try_wait.parity.acquire.cta.shared::cta.b64 P1, [%0], %1, 0x989680;\n\t" \
            "@P1 bra.uni D_%=;\n\t" \
            "bra.uni W_%=;\n\t" \
            "D_%=:\n\t}" :: "r"(_m), "r"(_p) : "memory"); \
    } } while (0)

__device__ __forceinline__ void bulk_cp(uint32_t dst, const void* src, uint32_t bytes,
                                        uint32_t mbar) {
    asm volatile(
        "cp.async.bulk.shared::cta.global.mbarrier::complete_tx::bytes [%0], [%1], %2, [%3];"
        :: "r"(dst), "l"(src), "r"(bytes), "r"(mbar) : "memory");
}

#if defined(__CUDA_ARCH_FEAT_SM103_ALL)
#define TC_ALLOC(sa, n) \
    asm volatile("tcgen05.alloc.cta_group::1.sync.aligned.shared::cta.b32 [%0], %1;" \
        :: "r"(sa), "r"(n) : "memory")
#define TC_RELINQ() \
    asm volatile("tcgen05.relinquish_alloc_permit.cta_group::1.sync.aligned;")
#define TC_DEALLOC(t, n) \
    asm volatile("tcgen05.dealloc.cta_group::1.sync.aligned.b32 %0, %1;" :: "r"(t), "r"(n))
#define TC_COMMIT(mb) \
    asm volatile("tcgen05.commit.cta_group::1.mbarrier::arrive::one.shared::cluster.b64 [%0];" \
        :: "r"(mb) : "memory")
#define TC_FENCE_AFTER() asm volatile("tcgen05.fence::after_thread_sync;" ::: "memory")
#define TC_FENCE_BEFORE() asm volatile("tcgen05.fence::before_thread_sync;" ::: "memory")
#define TC_WAIT_LD() asm volatile("tcgen05.wait::ld.sync.aligned;" ::: "memory")
#define TC_WAIT_ST() asm volatile("tcgen05.wait::st.sync.aligned;" ::: "memory")

#define TC_LD_X32(r, ta) \
    asm volatile("tcgen05.ld.sync.aligned.32x32b.x32.b32 " \
        "{%0, %1, %2, %3, %4, %5, %6, %7, %8, %9, %10, %11, %12, %13, %14, %15, " \
        "%16, %17, %18, %19, %20, %21, %22, %23, %24, %25, %26, %27, %28, %29, %30, %31}, [%32];" \
        : "=r"((r)[0]), "=r"((r)[1]), "=r"((r)[2]), "=r"((r)[3]), \
          "=r"((r)[4]), "=r"((r)[5]), "=r"((r)[6]), "=r"((r)[7]), \
          "=r"((r)[8]), "=r"((r)[9]), "=r"((r)[10]), "=r"((r)[11]), \
          "=r"((r)[12]), "=r"((r)[13]), "=r"((r)[14]), "=r"((r)[15]), \
          "=r"((r)[16]), "=r"((r)[17]), "=r"((r)[18]), "=r"((r)[19]), \
          "=r"((r)[20]), "=r"((r)[21]), "=r"((r)[22]), "=r"((r)[23]), \
          "=r"((r)[24]), "=r"((r)[25]), "=r"((r)[26]), "=r"((r)[27]), \
          "=r"((r)[28]), "=r"((r)[29]), "=r"((r)[30]), "=r"((r)[31]) \
        : "r"(ta))

#define TC_ST_X32(ta, r) \
    asm volatile("tcgen05.st.sync.aligned.32x32b.x32.b32 [%0], " \
        "{%1, %2, %3, %4, %5, %6, %7, %8, %9, %10, %11, %12, %13, %14, %15, %16, " \
        "%17, %18, %19, %20, %21, %22, %23, %24, %25, %26, %27, %28, %29, %30, %31, %32};" \
        :: "r"(ta), \
           "r"((r)[0]), "r"((r)[1]), "r"((r)[2]), "r"((r)[3]), \
           "r"((r)[4]), "r"((r)[5]), "r"((r)[6]), "r"((r)[7]), \
           "r"((r)[8]), "r"((r)[9]), "r"((r)[10]), "r"((r)[11]), \
           "r"((r)[12]), "r"((r)[13]), "r"((r)[14]), "r"((r)[15]), \
           "r"((r)[16]), "r"((r)[17]), "r"((r)[18]), "r"((r)[19]), \
           "r"((r)[20]), "r"((r)[21]), "r"((r)[22]), "r"((r)[23]), \
           "r"((r)[24]), "r"((r)[25]), "r"((r)[26]), "r"((r)[27]), \
           "r"((r)[28]), "r"((r)[29]), "r"((r)[30]), "r"((r)[31]) \
        : "memory")

__device__ __forceinline__ void mma_f16_ss(uint32_t d, uint64_t ad, uint64_t bd,
                                           uint32_t idesc, bool acc) {
    uint32_t en = acc ? 1u : 0u;
    asm volatile(
        "{\n\t.reg .pred p;\n\t"
        "setp.ne.u32 p, %5, 0;\n\t"
        "tcgen05.mma.cta_group::1.kind::f16 [%0], %1, %2, %3, {%4, %4, %4, %4}, p;\n\t"
        "}"
        :: "r"(d), "l"(ad), "l"(bd), "r"(idesc), "r"(0u), "r"(en)
        : "memory");
}
__device__ __forceinline__ void mma_f16_ts(uint32_t d, uint32_t a, uint64_t bd,
                                           uint32_t idesc, bool acc) {
    uint32_t en = acc ? 1u : 0u;
    asm volatile(
        "{\n\t.reg .pred p;\n\t"
        "setp.ne.u32 p, %5, 0;\n\t"
        "tcgen05.mma.cta_group::1.kind::f16 [%0], [%1], %2, %3, {%4, %4, %4, %4}, p;\n\t"
        "}"
        :: "r"(d), "r"(a), "l"(bd), "r"(idesc), "r"(0u), "r"(en)
        : "memory");
}
#endif

static constexpr uint64_t DESC_BASE_SW128 =
    (2ull << 61) | (1ull << 46) | (64ull << 32) | (1ull << 16);
__device__ __forceinline__ uint64_t make_desc(uint32_t addr) {
    return DESC_BASE_SW128 | ((uint64_t)(addr >> 4) & 0x3FFF);
}

#define IDESC_N256 ((1u << 4) | (1u << 7) | (1u << 10) | ((256u / 8) << 17) | ((128u / 16) << 24))
#define IDESC_N128 ((1u << 4) | (1u << 7) | (1u << 10) | ((128u / 8) << 17) | ((128u / 16) << 24))
#define IDESC_N64  ((1u << 4) | (1u << 7) | (1u << 10) | ((64u  / 8) << 17) | ((128u / 16) << 24))

#define GT_SMEM_TOTAL (1024 + 3 * 49152)
#define AT_QHI   2048
#define AT_QLO   18432
#define AT_KHI   34816
#define AT_KLO   51200
#define AT_VHI_A 67584
#define AT_VHI_B 75776
#define AT_VLO_A 83968
#define AT_VLO_B 92160
#define AT_SMEM_TOTAL 100352

// ---------------- prep: weights + mask bits ----------------
__global__ __launch_bounds__(256)
void prep_all_kernel(const float* __restrict__ Wq, const float* __restrict__ Wk,
                     const float* __restrict__ Wv, const float* __restrict__ Wo,
                     const float* __restrict__ W1, const float* __restrict__ W2,
                     __nv_bfloat16* __restrict__ wprep,
                     const float* __restrict__ mask, uint32_t* __restrict__ bits) {
    int bx = blockIdx.x;
    if (bx < 72) {
        int w = bx / 12, c = bx % 12;
        const float* W = (w == 0) ? Wq : (w == 1) ? Wk : (w == 2) ? Wv
                       : (w == 3) ? Wo : (w == 4) ? W1 : W2;
        int g = c / 3, t = c % 3, n = threadIdx.x;
        char* base = (char*)wprep + ((size_t)w * 12 + c) * 32768;
        #pragma unroll 4
        for (int j = 0; j < 64; j += 2) {
            float x0 = W[(size_t)(64 * g + j) * 256 + n];
            float x1 = W[(size_t)(64 * g + j + 1) * 256 + n];
            unsigned short h0 = (t == 2) ? f2bf_lo(x0) : f2bf(x0);
            unsigned short h1 = (t == 2) ? f2bf_lo(x1) : f2bf(x1);
            uint32_t off = n * 128 + j * 2;
            off ^= (off >> 3) & 0x70;
            *(uint32_t*)(base + off) = pack2(h0, h1);
        }
    } else {
        int idx = bx - 72;
        int lev = idx >> 6, rblk = idx & 63;
        int w = threadIdx.x >> 5, l = threadIdx.x & 31;
        int r = rblk * 8 + w;
        const float* row = mask + ((size_t)lev * NQ + r) * NK;
        uint32_t myword = 0;
        for (int j = 0; j < 32; j++) {
            uint32_t bal = __ballot_sync(0xffffffffu, row[j * 32 + l] > 0.5f);
            if (l == j) myword = bal;
        }
        bits[((size_t)lev * NQ + r) * 32 + l] = myword;
    }
}

// ---------------- gather + LN -> images: warp per row ----------------
__global__ __launch_bounds__(256)
void gather_ln_img_kernel(const float* __restrict__ emb, const float* __restrict__ upd,
                          const int* __restrict__ qi, const int* __restrict__ ki,
                          const float* __restrict__ sc, const float* __restrict__ bi,
                          unsigned char* __restrict__ imgq, unsigned char* __restrict__ imgk) {
    int wid = threadIdx.x >> 5, lane = threadIdx.x & 31;
    int i = blockIdx.x * 8 + wid;
    int b = i / (NQ + NK), rr = i % (NQ + NK);
    const int* idx;
    unsigned char* img;
    int r2, nrows;
    if (rr < NQ) { idx = qi; img = imgq; r2 = rr; nrows = NQ; }
    else         { idx = ki; img = imgk; r2 = rr - NQ; nrows = NK; }
    int j = __ldg(&idx[r2]);
    const float* e = emb + (size_t)j * Dm + lane * 8;
    const float* u = upd + ((size_t)b * NS + j) * Dm + lane * 8;
    float4 e0 = *(const float4*)e, e1 = *(const float4*)(e + 4);
    float4 u0 = *(const float4*)u, u1 = *(const float4*)(u + 4);
    float x[8] = {e0.x + u0.x, e0.y + u0.y, e0.z + u0.z, e0.w + u0.w,
                  e1.x + u1.x, e1.y + u1.y, e1.z + u1.z, e1.w + u1.w};
    float s = 0.f, q = 0.f;
    #pragma unroll
    for (int k = 0; k < 8; k++) { s += x[k]; q += x[k] * x[k]; }
    #pragma unroll
    for (int o = 16; o > 0; o >>= 1) {
        s += __shfl_xor_sync(0xffffffffu, s, o);
        q += __shfl_xor_sync(0xffffffffu, q, o);
    }
    float m = s * (1.0f / Dm);
    float var = q * (1.0f / Dm) - m * m;
    float rs = rsqrtf(fmaxf(var, 0.f) + 1e-5f);
    float4 s0 = *(const float4*)(sc + lane * 8), s1 = *(const float4*)(sc + lane * 8 + 4);
    float4 b0 = *(const float4*)(bi + lane * 8), b1 = *(const float4*)(bi + lane * 8 + 4);
    float y[8];
    y[0] = (x[0] - m) * rs * s0.x + b0.x; y[1] = (x[1] - m) * rs * s0.y + b0.y;
    y[2] = (x[2] - m) * rs * s0.z + b0.z; y[3] = (x[3] - m) * rs * s0.w + b0.w;
    y[4] = (x[4] - m) * rs * s1.x + b1.x; y[5] = (x[5] - m) * rs * s1.y + b1.y;
    y[6] = (x[6] - m) * rs * s1.z + b1.z; y[7] = (x[7] - m) * rs * s1.w + b1.w;
    int row = b * nrows + r2;
    int tile = row >> 7, r7 = row & 127;
    int g = lane >> 3;
    uint32_t off = r7 * 128 + ((lane * 8) & 63) * 2;
    off ^= (off >> 3) & 0x70;
    uint4 hv, lv;
    packhilo(y[0], y[1], hv.x, lv.x);
    packhilo(y[2], y[3], hv.y, lv.y);
    packhilo(y[4], y[5], hv.z, lv.z);
    packhilo(y[6], y[7], hv.w, lv.w);
    *(uint4*)(img + img_off(tile, g, 0) + off) = hv;
    *(uint4*)(img + img_off(tile, g, 1) + off) = lv;
}

// ---------------- tc GEMM shared pieces ----------------
__device__ __forceinline__ uint32_t tc_gemm_start(uint32_t sb) {
    uint32_t tmem = 0;
#if defined(__CUDA_ARCH_FEAT_SM103_ALL)
    int tid = threadIdx.x, wid = tid >> 5;
    if (wid == 0) { TC_ALLOC(sb + 0, 256); TC_RELINQ(); }
    if (tid == 0) {
        #pragma unroll
        for (int i = 0; i < 7; i++) MBAR_INIT(sb + 16 + 8 * i, 1);
    }
    __syncthreads();
    asm volatile("ld.shared.b32 %0, [%1];" : "=r"(tmem) : "r"(sb + 0));
#endif
    return tmem;
}

__device__ __forceinline__ void tc_gemm_mainloop(const unsigned char* __restrict__ Aimg,
                                                 const __nv_bfloat16* __restrict__ Wp,
                                                 int tile, uint32_t sb, uint32_t tmem) {
#if defined(__CUDA_ARCH_FEAT_SM103_ALL)
    if (threadIdx.x == 0) {
        auto issue_chunk = [&](int c, int s) {
            int g = c / 3, tt = c % 3;
            int aidx = tile * 8 + g * 2 + (tt == 1 ? 1 : 0);
            uint32_t fm = sb + 16 + 8 * s;
            uint32_t sa = sb + 1024 + s * 49152;
            MBAR_EXPECT(fm, 49152);
            bulk_cp(sa, Aimg + ((size_t)aidx << 14), 16384, fm);
            bulk_cp(sa + 16384, (const unsigned char*)Wp + ((size_t)c << 15), 32768, fm);
        };
        issue_chunk(0, 0); issue_chunk(1, 1); issue_chunk(2, 2);
        int fph0 = 0, fph1 = 0, fph2 = 0, dph0 = 0, dph1 = 0, dph2 = 0;
        for (int c = 0; c < 12; c++) {
            int s = c % 3;
            int fp = (s == 0) ? fph0 : (s == 1) ? fph1 : fph2;
            MBAR_WAIT(sb + 16 + 8 * s, fp);
            if (s == 0) fph0 ^= 1; else if (s == 1) fph1 ^= 1; else fph2 ^= 1;
            uint32_t sa = sb + 1024 + s * 49152;
            uint64_t ad = make_desc(sa);
            uint64_t bd = make_desc(sa + 16384);
            #pragma unroll
            for (int k = 0; k < 4; k++)
                mma_f16_ss(tmem, ad + 2 * k, bd + 2 * k, IDESC_N256, (c > 0) || (k > 0));
            if (c <= 8) {
                TC_COMMIT(sb + 40 + 8 * s);
                int dp = (s == 0) ? dph0 : (s == 1) ? dph1 : dph2;
                MBAR_WAIT(sb + 40 + 8 * s, dp);
                if (s == 0) dph0 ^= 1; else if (s == 1) dph1 ^= 1; else dph2 ^= 1;
                issue_chunk(c + 3, s);
            } else if (c == 11) {
                TC_COMMIT(sb + 64);
            }
        }
    }
    MBAR_WAIT(sb + 64, 0);
    TC_FENCE_AFTER();
    __syncthreads();
#endif
}

__device__ __forceinline__ void tc_gemm_end(uint32_t sb, uint32_t tmem) {
#if defined(__CUDA_ARCH_FEAT_SM103_ALL)
    __syncthreads();
    if (threadIdx.x == 0) {
        #pragma unroll
        for (int i = 0; i < 7; i++) MBAR_INVAL(sb + 16 + 8 * i);
    }
    __syncthreads();
    if ((threadIdx.x >> 5) == 0) TC_DEALLOC(tmem, 256);
#endif
}

// ---------------- GEMM -> images (outmode 1: normal, 2: V transposed) ----------------
__device__ __forceinline__ void gemm_body_img(const unsigned char* __restrict__ Aimg,
                                              const __nv_bfloat16* __restrict__ Wp,
                                              const float* __restrict__ bias,
                                              unsigned char* __restrict__ Cimg,
                                              int tile, int epi, int outmode) {
#if defined(__CUDA_ARCH_FEAT_SM103_ALL)
    extern __shared__ char smem[];
    uint32_t sb = smem_u32(smem);
    int tid = threadIdx.x, wid = tid >> 5, lane = tid & 31;
    uint32_t tmem = tc_gemm_start(sb);
    tc_gemm_mainloop(Aimg, Wp, tile, sb, tmem);

    int sp = wid & 3, hf = wid >> 2;
    int rr = sp * 32 + lane;
    for (int p = hf * 4; p < hf * 4 + 4; p++) {
        uint32_t regs[32];
        TC_LD_X32(regs, tmem + p * 32);
        TC_WAIT_LD();
        float v[32];
        #pragma unroll
        for (int j = 0; j < 32; j++) {
            float u = __uint_as_float(regs[j]);
            if (epi >= 1) u += bias[p * 32 + j];
            if (epi == 2) u = gelu_tanh(u);
            v[j] = u;
        }
        if (outmode == 1) {
            unsigned char* hi = Cimg + img_off(tile, p >> 1, 0);
            unsigned char* lo = Cimg + img_off(tile, p >> 1, 1);
            int cb = (p & 1) * 32;
            #pragma unroll
            for (int j = 0; j < 32; j += 2) {
                uint32_t off = rr * 128 + (cb + j) * 2;
                off ^= (off >> 3) & 0x70;
                uint32_t hw, lw;
                packhilo(v[j], v[j + 1], hw, lw);
                *(uint32_t*)(hi + off) = hw;
                *(uint32_t*)(lo + off) = lw;
            }
        } else {
            int kv = rr & 63, half = rr >> 6;
            unsigned char* hi = Cimg + imgv_off(tile, p >> 1, half, 0);
            unsigned char* lo = Cimg + imgv_off(tile, p >> 1, half, 1);
            #pragma unroll
            for (int j = 0; j < 32; j++) {
                int dd = (p & 1) * 32 + j;
                uint32_t off = dd * 128 + kv * 2;
                off ^= (off >> 3) & 0x70;
                *(unsigned short*)(hi + off) = f2bf(v[j]);
                *(unsigned short*)(lo + off) = f2bf_lo(v[j]);
            }
        }
    }
    tc_gemm_end(sb, tmem);
#endif
}

// merged QKV: grid = 128 + 256 + 256
__global__ __launch_bounds__(256)
void qkv_tc_kernel(const unsigned char* __restrict__ qnImg,
                   const unsigned char* __restrict__ knImg,
                   const __nv_bfloat16* __restrict__ wprep,
                   unsigned char* __restrict__ imgQ,
                   unsigned char* __restrict__ imgK,
                   unsigned char* __restrict__ imgVt) {
    const size_t WCH = (size_t)12 * 256 * 64;
    int bx = blockIdx.x;
    if (bx < 128)
        gemm_body_img(qnImg, wprep + 0 * WCH, nullptr, imgQ, bx, 0, 1);
    else if (bx < 384)
        gemm_body_img(knImg, wprep + 1 * WCH, nullptr, imgK, bx - 128, 0, 1);
    else
        gemm_body_img(knImg, wprep + 2 * WCH, nullptr, imgVt, bx - 384, 0, 2);
}

// ffn1: gelu epilogue -> images
__global__ __launch_bounds__(256)
void ffn1_tc_kernel(const unsigned char* __restrict__ Aimg,
                    const __nv_bfloat16* __restrict__ Wp,
                    const float* __restrict__ bias,
                    unsigned char* __restrict__ Cimg) {
    gemm_body_img(Aimg, Wp, bias, Cimg, blockIdx.x, 2, 1);
}

// ---------------- Wo GEMM + inner LN fused ----------------
__global__ __launch_bounds__(256)
void wo_ln_kernel(const unsigned char* __restrict__ Aimg,
                  const __nv_bfloat16* __restrict__ Wp,
                  const float* __restrict__ in_s, const float* __restrict__ in_b,
                  float* __restrict__ hOut, unsigned char* __restrict__ hImg) {
#if defined(__CUDA_ARCH_FEAT_SM103_ALL)
    extern __shared__ char smem[];
    uint32_t sb = smem_u32(smem);
    int tid = threadIdx.x, wid = tid >> 5, lane = tid & 31;
    int tile = blockIdx.x;
    uint32_t tmem = tc_gemm_start(sb);
    tc_gemm_mainloop(Aimg, Wp, tile, sb, tmem);

    float* stage = (float*)(smem + 1024);            // [128][257]
    float* redS  = (float*)(smem + 1024 + 131584);   // [128][4]
    int sp = wid & 3, hf = wid >> 2;
    int rr = sp * 32 + lane;
    float psum = 0.f, psq = 0.f;
    for (int p = hf * 4; p < hf * 4 + 4; p++) {
        uint32_t regs[32];
        TC_LD_X32(regs, tmem + p * 32);
        TC_WAIT_LD();
        #pragma unroll
        for (int j = 0; j < 32; j++) {
            float v = __uint_as_float(regs[j]);
            psum += v; psq += v * v;
            stage[rr * 257 + p * 32 + j] = v;
        }
    }
    redS[rr * 4 + hf * 2] = psum;
    redS[rr * 4 + hf * 2 + 1] = psq;
    __syncthreads();
    float m = (redS[rr * 4] + redS[rr * 4 + 2]) * (1.0f / Dm);
    float var = (redS[rr * 4 + 1] + redS[rr * 4 + 3]) * (1.0f / Dm) - m * m;
    float rs = rsqrtf(fmaxf(var, 0.f) + 1e-5f);
    int row = tile * 128 + rr;
    for (int p = hf * 4; p < hf * 4 + 4; p++) {
        float y[32];
        #pragma unroll
        for (int j = 0; j < 32; j++) {
            int col = p * 32 + j;
            y[j] = (stage[rr * 257 + col] - m) * rs * in_s[col] + in_b[col];
        }
        #pragma unroll
        for (int j = 0; j < 32; j += 4)
            *(float4*)&hOut[(size_t)row * Dm + p * 32 + j] =
                make_float4(y[j], y[j + 1], y[j + 2], y[j + 3]);
        unsigned char* hi = hImg + img_off(tile, p >> 1, 0);
        unsigned char* lo = hImg + img_off(tile, p >> 1, 1);
        int cb = (p & 1) * 32;
        #pragma unroll
        for (int j = 0; j < 32; j += 2) {
            uint32_t off = rr * 128 + (cb + j) * 2;
            off ^= (off >> 3) & 0x70;
            uint32_t hw, lw;
            packhilo(y[j], y[j + 1], hw, lw);
            *(uint32_t*)(hi + off) = hw;
            *(uint32_t*)(lo + off) = lw;
        }
    }
    tc_gemm_end(sb, tmem);
#endif
}

// ---------------- ffn2 GEMM + residual + double LN + scatter fused ----------------
__global__ __launch_bounds__(256)
void ffn2_scatter_kernel(const unsigned char* __restrict__ Aimg,
                         const __nv_bfloat16* __restrict__ Wp,
                         const float* __restrict__ b2,
                         const float* __restrict__ hBuf,
                         const int* __restrict__ qi,
                         const float* __restrict__ os, const float* __restrict__ ob,
                         const float* __restrict__ es, const float* __restrict__ eb,
                         float* __restrict__ upd, float* __restrict__ out) {
#if defined(__CUDA_ARCH_FEAT_SM103_ALL)
    extern __shared__ char smem[];
    uint32_t sb = smem_u32(smem);
    int tid = threadIdx.x, wid = tid >> 5, lane = tid & 31;
    int tile = blockIdx.x;
    uint32_t tmem = tc_gemm_start(sb);
    tc_gemm_mainloop(Aimg, Wp, tile, sb, tmem);

    float* stage = (float*)(smem + 1024);                      // [128][257]
    float* redS  = (float*)(smem + 1024 + 131584);             // [128][4]
    float* rm2   = (float*)(smem + 1024 + 131584 + 2048);      // [128]
    float* rr2   = rm2 + 128;                                  // [128]
    unsigned long long* rowbase = (unsigned long long*)(rr2 + 128);  // [128]

    int sp = wid & 3, hf = wid >> 2;
    int rr = sp * 32 + lane;
    int row = tile * 128 + rr;

    float psum = 0.f, psq = 0.f;
    for (int p = hf * 4; p < hf * 4 + 4; p++) {
        uint32_t regs[32];
        TC_LD_X32(regs, tmem + p * 32);
        TC_WAIT_LD();
        #pragma unroll
        for (int j = 0; j < 32; j += 4) {
            float4 hv = *(const float4*)&hBuf[(size_t)row * Dm + p * 32 + j];
            float x0 = __uint_as_float(regs[j])     + b2[p * 32 + j]     + hv.x;
            float x1 = __uint_as_float(regs[j + 1]) + b2[p * 32 + j + 1] + hv.y;
            float x2 = __uint_as_float(regs[j + 2]) + b2[p * 32 + j + 2] + hv.z;
            float x3 = __uint_as_float(regs[j + 3]) + b2[p * 32 + j + 3] + hv.w;
            psum += x0 + x1 + x2 + x3;
            psq  += x0 * x0 + x1 * x1 + x2 * x2 + x3 * x3;
            stage[rr * 257 + p * 32 + j]     = x0;
            stage[rr * 257 + p * 32 + j + 1] = x1;
            stage[rr * 257 + p * 32 + j + 2] = x2;
            stage[rr * 257 + p * 32 + j + 3] = x3;
        }
    }
    redS[rr * 4 + hf * 2] = psum;
    redS[rr * 4 + hf * 2 + 1] = psq;
    if (tid < 128) {
        int g = tile * 128 + tid;
        int b = g >> 9, r = g & 511;
        rowbase[tid] = ((unsigned long long)b * NS + qi[r]) * Dm;
    }
    __syncthreads();
    float m1 = (redS[rr * 4] + redS[rr * 4 + 2]) * (1.0f / Dm);
    float v1 = (redS[rr * 4 + 1] + redS[rr * 4 + 3]) * (1.0f / Dm) - m1 * m1;
    float rs1 = rsqrtf(fmaxf(v1, 0.f) + 1e-5f);
    __syncthreads();

    float psum2 = 0.f, psq2 = 0.f;
    for (int p = hf * 4; p < hf * 4 + 4; p++) {
        #pragma unroll
        for (int j = 0; j < 32; j++) {
            int col = p * 32 + j;
            float y = (stage[rr * 257 + col] - m1) * rs1 * os[col] + ob[col];
            stage[rr * 257 + col] = y;
            psum2 += y; psq2 += y * y;
        }
    }
    __syncthreads();
    redS[rr * 4 + hf * 2] = psum2;
    redS[rr * 4 + hf * 2 + 1] = psq2;
    __syncthreads();
    if (hf == 0) {
        float m2 = (redS[rr * 4] + redS[rr * 4 + 2]) * (1.0f / Dm);
        float v2 = (redS[rr * 4 + 1] + redS[rr * 4 + 3]) * (1.0f / Dm) - m2 * m2;
        rm2[rr] = m2;
        rr2[rr] = rsqrtf(fmaxf(v2, 0.f) + 1e-5f);
    }
    __syncthreads();

    float est = es[tid], ebt = eb[tid];
    for (int i = 0; i < 128; i++) {
        float y = stage[i * 257 + tid];
        float res = (y - rm2[i]) * rr2[i] * est + ebt;
        unsigned long long o = rowbase[i] + tid;
        atomicAdd(&upd[o], res);
        atomicAdd(&out[o], res);
    }
    tc_gemm_end(sb, tmem);
#endif
}

// ---------------- tc flash attention ----------------
__global__ __launch_bounds__(256, 2)
void attn_tc_kernel(const unsigned char* __restrict__ Qimg,
                    const unsigned char* __restrict__ Kimg,
                    const unsigned char* __restrict__ Vimg,
                    const uint32_t* __restrict__ mbits,
                    unsigned char* __restrict__ ctxImg) {
#if defined(__CUDA_ARCH_FEAT_SM103_ALL)
    extern __shared__ char smem[];
    uint32_t sb = smem_u32(smem);
    int qt = blockIdx.x, h = blockIdx.y, b = blockIdx.z;
    int tid = threadIdx.x, wid = tid >> 5, lane = tid & 31;
    int sp = wid & 3, hf = wid >> 2;
    float* redA = (float*)(smem + 64);
    float* redB = (float*)(smem + 64 + 512);

    if (wid == 0) { TC_ALLOC(sb + 0, 256); TC_RELINQ(); }
    if (tid == 0) {
        MBAR_INIT(sb + 16, 1);
        MBAR_INIT(sb + 24, 1);
        MBAR_INIT(sb + 32, 1);
        MBAR_INIT(sb + 40, 1);
        MBAR_INIT(sb + 48, 1);
    }
    __syncthreads();
    uint32_t tmem;
    asm volatile("ld.shared.b32 %0, [%1];" : "=r"(tmem) : "r"(sb + 0));

    auto issueK = [&](int t) {
        int kt = b * 8 + t;
        MBAR_EXPECT(sb + 32, 32768);
        bulk_cp(sb + AT_KHI, Kimg + img_off(kt, h, 0), 16384, sb + 32);
        bulk_cp(sb + AT_KLO, Kimg + img_off(kt, h, 1), 16384, sb + 32);
    };
    auto issueV = [&](int t) {
        int kt = b * 8 + t;
        MBAR_EXPECT(sb + 40, 32768);
        bulk_cp(sb + AT_VHI_A, Vimg + imgv_off(kt, h, 0, 0), 8192, sb + 40);
        bulk_cp(sb + AT_VHI_B, Vimg + imgv_off(kt, h, 1, 0), 8192, sb + 40);
        bulk_cp(sb + AT_VLO_A, Vimg + imgv_off(kt, h, 0, 1), 8192, sb + 40);
        bulk_cp(sb + AT_VLO_B, Vimg + imgv_off(kt, h, 1, 1), 8192, sb + 40);
    };
    if (tid == 0) {
        MBAR_EXPECT(sb + 48, 32768);
        bulk_cp(sb + AT_QHI, Qimg + img_off(b * 4 + qt, h, 0), 16384, sb + 48);
        bulk_cp(sb + AT_QLO, Qimg + img_off(b * 4 + qt, h, 1), 16384, sb + 48);
        issueK(0);
        issueV(0);
    }

    int qrow = sp * 32 + lane;
    const uint32_t* rowbits = mbits + (size_t)(qt * 128 + qrow) * 32 + hf * 2;
    float mrow = -1e30f, lrow = 0.f;
    float acc[32];
    #pragma unroll
    for (int j = 0; j < 32; j++) acc[j] = 0.f;

    int ph1 = 0, ph2 = 0, kph = 0, vph = 0;

    for (int t = 0; t < 8; t++) {
        int k0 = t * 128;
        if (tid == 0) {
            if (t == 0) MBAR_WAIT(sb + 48, 0);
            MBAR_WAIT(sb + 32, kph);
            uint64_t qhiD = make_desc(sb + AT_QHI);
            uint64_t qloD = make_desc(sb + AT_QLO);
            uint64_t khiD = make_desc(sb + AT_KHI);
            uint64_t kloD = make_desc(sb + AT_KLO);
            bool first = true;
            #pragma unroll
            for (int k = 0; k < 4; k++) { mma_f16_ss(tmem, qhiD + 2 * k, khiD + 2 * k, IDESC_N128, !first); first = false; }
            #pragma unroll
            for (int k = 0; k < 4; k++) mma_f16_ss(tmem, qloD + 2 * k, khiD + 2 * k, IDESC_N128, true);
            #pragma unroll
            for (int k = 0; k < 4; k++) mma_f16_ss(tmem, qhiD + 2 * k, kloD + 2 * k, IDESC_N128, true);
            TC_COMMIT(sb + 16);
        }
        kph ^= 1;
        MBAR_WAIT(sb + 16, ph1); ph1 ^= 1;
        TC_FENCE_AFTER();
        if (tid == 0 && t < 7) issueK(t + 1);

        uint32_t sr[32];
        float s[64];
        TC_LD_X32(sr, tmem + hf * 64);
        TC_WAIT_LD();
        uint32_t w0 = rowbits[(k0 >> 5)];
        #pragma unroll
        for (int j = 0; j < 32; j++)
            s[j] = ((w0 >> j) & 1u) ? __uint_as_float(sr[j]) * ATT_SCALE : -1e9f;
        TC_LD_X32(sr, tmem + hf * 64 + 32);
        TC_WAIT_LD();
        uint32_t w1 = rowbits[(k0 >> 5) + 1];
        #pragma unroll
        for (int j = 0; j < 32; j++)
            s[32 + j] = ((w1 >> j) & 1u) ? __uint_as_float(sr[j]) * ATT_SCALE : -1e9f;

        float mloc = -1e30f;
        #pragma unroll
        for (int j = 0; j < 64; j++) mloc = fmaxf(mloc, s[j]);
        (hf ? redB : redA)[qrow] = mloc;
        __syncthreads();
        float mx = fmaxf(redA[qrow], redB[qrow]);
        float mnew = fmaxf(mrow, mx);
        float alpha = __expf(mrow - mnew);
        mrow = mnew;
        __syncthreads();
        float ps = 0.f;
        #pragma unroll
        for (int j = 0; j < 64; j++) {
            float p = __expf(s[j] - mnew);
            s[j] = p;
            ps += p;
        }
        (hf ? redB : redA)[qrow] = ps;
        __syncthreads();
        lrow = lrow * alpha + redA[qrow] + redB[qrow];

        uint32_t woff = (uint32_t)sp << 21;
        uint32_t pv[32];
        #pragma unroll
        for (int c = 0; c < 32; c++) CVT2(pv[c], s[2 * c], s[2 * c + 1]);
        TC_ST_X32(tmem + hf * 32 + woff, pv);
        #pragma unroll
        for (int c = 0; c < 32; c++) {
            float h0 = __uint_as_float(pv[c] << 16);
            float h1 = __uint_as_float(pv[c] & 0xFFFF0000u);
            CVT2(pv[c], s[2 * c] - h0, s[2 * c + 1] - h1);
        }
        TC_ST_X32(tmem + 64 + hf * 32 + woff, pv);
        TC_WAIT_ST();
        TC_FENCE_BEFORE();
        __syncthreads();

        if (tid == 0) {
            MBAR_WAIT(sb + 40, vph);
            TC_FENCE_AFTER();
            uint64_t vhiA = make_desc(sb + AT_VHI_A);
            uint64_t vhiB = make_desc(sb + AT_VHI_B);
            uint64_t vloA = make_desc(sb + AT_VLO_A);
            uint64_t vloB = make_desc(sb + AT_VLO_B);
            bool first = true;
            #pragma unroll
            for (int s8 = 0; s8 < 8; s8++) {
                uint64_t bd = (s8 < 4 ? vhiA + 2 * s8 : vhiB + 2 * (s8 - 4));
                mma_f16_ts(tmem + 128, tmem + 0 + s8 * 8, bd, IDESC_N64, !first);
                first = false;
            }
            #pragma unroll
            for (int s8 = 0; s8 < 8; s8++) {
                uint64_t bd = (s8 < 4 ? vhiA + 2 * s8 : vhiB + 2 * (s8 - 4));
                mma_f16_ts(tmem + 128, tmem + 64 + s8 * 8, bd, IDESC_N64, true);
            }
            #pragma unroll
            for (int s8 = 0; s8 < 8; s8++) {
                uint64_t bd = (s8 < 4 ? vloA + 2 * s8 : vloB + 2 * (s8 - 4));
                mma_f16_ts(tmem + 128, tmem + 0 + s8 * 8, bd, IDESC_N64, true);
            }
            TC_COMMIT(sb + 24);
        }
        vph ^= 1;
        MBAR_WAIT(sb + 24, ph2); ph2 ^= 1;
        TC_FENCE_AFTER();
        if (tid == 0 && t < 7) issueV(t + 1);

        uint32_t dr[32];
        TC_LD_X32(dr, tmem + 128 + hf * 32);
        TC_WAIT_LD();
        TC_FENCE_BEFORE();
        #pragma unroll
        for (int j = 0; j < 32; j++)
            acc[j] = acc[j] * alpha + __uint_as_float(dr[j]);
    }

    {
        float invl = 1.0f / lrow;
        unsigned char* chi = ctxImg + img_off(b * 4 + qt, h, 0);
        unsigned char* clo = ctxImg + img_off(b * 4 + qt, h, 1);
        #pragma unroll
        for (int j = 0; j < 32; j += 2) {
            float v0 = acc[j] * invl, v1 = acc[j + 1] * invl;
            uint32_t off = qrow * 128 + (hf * 32 + j) * 2;
            off ^= (off >> 3) & 0x70;
            uint32_t hw, lw;
            packhilo(v0, v1, hw, lw);
            *(uint32_t*)(chi + off) = hw;
            *(uint32_t*)(clo + off) = lw;
        }
    }

    __syncthreads();
    if (tid == 0) {
        MBAR_INVAL(sb + 16); MBAR_INVAL(sb + 24); MBAR_INVAL(sb + 32);
        MBAR_INVAL(sb + 40); MBAR_INVAL(sb + 48);
    }
    __syncthreads();
    if (wid == 0) TC_DEALLOC(tmem, 256);
#endif
}

// ---------------- host launcher ----------------
extern "C" void kernel_launch(void* const* d_in, const int* in_sizes, int n_in,
                              void* d_out, int out_size) {
    const float* update = (const float*)d_in[0];
    const float* emb    = (const float*)d_in[1];
    const float* mask   = (const float*)d_in[2];
    const float* Wq     = (const float*)d_in[3];
    const float* Wk     = (const float*)d_in[4];
    const float* Wv     = (const float*)d_in[5];
    const float* Wo     = (const float*)d_in[6];
    const float* W1     = (const float*)d_in[7];
    const float* b1     = (const float*)d_in[8];
    const float* W2     = (const float*)d_in[9];
    const float* b2     = (const float*)d_in[10];
    const float* sys_s  = (const float*)d_in[11];
    const float* sys_b  = (const float*)d_in[12];
    const float* eff_s  = (const float*)d_in[13];
    const float* eff_b  = (const float*)d_in[14];
    const float* in_s   = (const float*)d_in[15];
    const float* in_b   = (const float*)d_in[16];
    const float* out_s  = (const float*)d_in[17];
    const float* out_b  = (const float*)d_in[18];
    const int*   qidx   = (const int*)d_in[19];
    const int*   kidx   = (const int*)d_in[20];
    float* out = (float*)d_out;

    float *p_upd, *p_h;
    uint32_t* p_mb;
    __nv_bfloat16* p_w;
    unsigned char *p_iqn, *p_ikn, *p_iQ, *p_iK, *p_iVt, *p_ictx, *p_ih, *p_it;
    cudaGetSymbolAddress((void**)&p_upd, g_upd);
    cudaGetSymbolAddress((void**)&p_h,   g_h);
    cudaGetSymbolAddress((void**)&p_mb,  g_mbits);
    cudaGetSymbolAddress((void**)&p_w,   g_wprep);
    cudaGetSymbolAddress((void**)&p_iqn, g_img_qn);
    cudaGetSymbolAddress((void**)&p_ikn, g_img_kn);
    cudaGetSymbolAddress((void**)&p_iQ,  g_img_Q);
    cudaGetSymbolAddress((void**)&p_iK,  g_img_K);
    cudaGetSymbolAddress((void**)&p_iVt, g_img_Vt);
    cudaGetSymbolAddress((void**)&p_ictx, g_img_ctx);
    cudaGetSymbolAddress((void**)&p_ih,  g_img_h);
    cudaGetSymbolAddress((void**)&p_it,  g_img_t);

    cudaFuncSetAttribute(qkv_tc_kernel, cudaFuncAttributeMaxDynamicSharedMemorySize, GT_SMEM_TOTAL);
    cudaFuncSetAttribute(ffn1_tc_kernel, cudaFuncAttributeMaxDynamicSharedMemorySize, GT_SMEM_TOTAL);
    cudaFuncSetAttribute(wo_ln_kernel, cudaFuncAttributeMaxDynamicSharedMemorySize, GT_SMEM_TOTAL);
    cudaFuncSetAttribute(ffn2_scatter_kernel, cudaFuncAttributeMaxDynamicSharedMemorySize, GT_SMEM_TOTAL);
    cudaFuncSetAttribute(attn_tc_kernel, cudaFuncAttributeMaxDynamicSharedMemorySize, AT_SMEM_TOTAL);

    const size_t WCH = (size_t)12 * 256 * 64;

    cudaMemsetAsync(d_out, 0, (size_t)out_size * sizeof(float), 0);
    cudaMemcpyAsync(p_upd, update, (size_t)Bz * NS * Dm * sizeof(float),
                    cudaMemcpyDeviceToDevice, 0);

    prep_all_kernel<<<72 + Ll * 64, 256>>>(Wq, Wk, Wv, Wo, W1, W2, p_w, mask, p_mb);

    for (int l = 0; l < Ll; l++) {
        const int* qi = qidx + l * NQ;
        const int* ki = kidx + l * NK;
        const uint32_t* mb = p_mb + (size_t)l * NQ * (NK / 32);

        gather_ln_img_kernel<<<(Bz * (NQ + NK)) / 8, 256>>>(emb, p_upd, qi, ki,
                                                            sys_s, sys_b, p_iqn, p_ikn);

        qkv_tc_kernel<<<640, 256, GT_SMEM_TOTAL>>>(p_iqn, p_ikn, p_w, p_iQ, p_iK, p_iVt);

        attn_tc_kernel<<<dim3(NQ / 128, Hh, Bz), 256, AT_SMEM_TOTAL>>>(p_iQ, p_iK, p_iVt, mb, p_ictx);

        wo_ln_kernel<<<128, 256, GT_SMEM_TOTAL>>>(p_ictx, p_w + 3 * WCH, in_s, in_b, p_h, p_ih);

        ffn1_tc_kernel<<<128, 256, GT_SMEM_TOTAL>>>(p_ih, p_w + 4 * WCH, b1, p_it);

        ffn2_scatter_kernel<<<128, 256, GT_SMEM_TOTAL>>>(p_it, p_w + 5 * WCH, b2, p_h, qi,
                                                         out_s, out_b, eff_s, eff_b,
                                                         p_upd, out);
    }
}